// round 14
// baseline (speedup 1.0000x reference)
#include <cuda_runtime.h>
#include <cstdint>

// Problem constants
#define T_DIM 1024
#define B_DIM 4
#define S_DIM 1024
#define E_DIM 1024
#define H_DIM 16
#define D_DIM 64
#define TB (T_DIM * B_DIM)
#define BE (B_DIM * E_DIM)

// Scratch (device globals — no allocation allowed)
__device__ float g_Q[TB * E_DIM];
__device__ float g_K[TB * E_DIM];
__device__ float g_V[TB * E_DIM];
__device__ float g_Ctx[TB * E_DIM];
__device__ float g_P[(long)B_DIM * H_DIM * T_DIM * S_DIM];   // scores -> probs (256 MB)

// Pre-converted tf32 stage images (frag-interleaved + rotation layout)
__device__ uint32_t g_QKVpre[(long)3 * 32 * 32 * 4096];   // 48 MB: 3 inputs, A-layout
__device__ uint32_t g_Wpre[(long)4 * 8 * 32 * 4096];      // 16 MB: wq,wk,wv,ow, B-layout
__device__ uint32_t g_Qpre[(long)64 * 8 * 8192];          // 16 MB: score A tiles (b,h,tblk)
__device__ uint32_t g_Kpre[(long)64 * 8 * 8192];          // 16 MB: score B tiles (b,h,sblk)

// ---------------------------------------------------------------------------
// tf32 helpers
// ---------------------------------------------------------------------------
__device__ __forceinline__ uint32_t f2tf(float x) {
    uint32_t r;
    asm("cvt.rna.tf32.f32 %0, %1;" : "=r"(r) : "f"(x));
    return r;
}

__device__ __forceinline__ void mma8(float* d, const uint32_t* a, const uint32_t* b) {
    asm volatile(
        "mma.sync.aligned.m16n8k8.row.col.f32.tf32.tf32.f32 "
        "{%0,%1,%2,%3}, {%4,%5,%6,%7}, {%8,%9}, {%0,%1,%2,%3};\n"
        : "+f"(d[0]), "+f"(d[1]), "+f"(d[2]), "+f"(d[3])
        : "r"(a[0]), "r"(a[1]), "r"(a[2]), "r"(a[3]), "r"(b[0]), "r"(b[1]));
}

#define PBK 32
#define LDA 132
#define GEMM_SMEM_BYTES (16384 * 4)   // 64 KB, 2 stages x (A 4096 + B 4096)

// ---------------------------------------------------------------------------
// prep_proj: build stage images for the projection GEMMs.
// blocks 0..95: input A-tiles (seg=bx/32 in {q,k,v}, mblk=bx%32)
// blocks 96..127: weight B-tiles (wseg=(bx-96)/8 in {wq,wk,wv,ow}, nblk=%8)
// Index formulas are verbatim from the validated GEMM_STAGE.
// ---------------------------------------------------------------------------
__global__ void __launch_bounds__(256) prep_proj(
    const float* __restrict__ query, const float* __restrict__ key,
    const float* __restrict__ value, const float* __restrict__ ipw,
    const float* __restrict__ ow,
    uint32_t* __restrict__ Apre, uint32_t* __restrict__ Bpre)
{
    const int tid = threadIdx.x;
    const int bx = blockIdx.x;
    const int lrow = tid >> 3, lkc = (tid & 7) << 2;
    const int sbq = lkc >> 3;
    const int fragk2 = ((lkc & 7) >= 4) ? 2 : 0;
    const int fragb  = ((lkc & 7) >= 4) ? 1 : 0;

    if (bx < 96) {
        const int seg = bx >> 5, mblk = bx & 31;
        const float* A = (seg == 0) ? query : (seg == 1) ? key : value;
        uint32_t* dstbase = Apre + (long)(seg * 32 + mblk) * (32 * 4096);
        const int m0 = mblk * 128;
        for (int it = 0; it < 32; it++) {
            uint32_t* dst = dstbase + it * 4096;
            const int k0 = it * 32;
            #pragma unroll
            for (int p = 0; p < 4; p++) {
                int row = lrow + p * 32;
                float4 a4 = *(const float4*)(A + (long)(m0 + row) * E_DIM + k0 + lkc);
                int mbq = row >> 4, fragm = ((row & 15) >= 8) ? 1 : 0;
                int laneb = (row & 7) * 4;
                int R = (row + sbq) & 3;
                uint32_t* aw = dst + ((sbq * 8 + mbq) * 32 + laneb) * 4 + fragk2 + fragm;
                aw[4 * ((0 + R) & 3)] = f2tf(a4.x);
                aw[4 * ((1 + R) & 3)] = f2tf(a4.y);
                aw[4 * ((2 + R) & 3)] = f2tf(a4.z);
                aw[4 * ((3 + R) & 3)] = f2tf(a4.w);
            }
        }
    } else {
        const int t = bx - 96;
        const int wseg = t >> 3, nblk = t & 7;
        const float* W = (wseg < 3) ? (ipw + (long)wseg * E_DIM * E_DIM) : ow;
        uint32_t* dstbase = Bpre + (long)(wseg * 8 + nblk) * (32 * 4096);
        const int n0 = nblk * 128;
        for (int it = 0; it < 32; it++) {
            uint32_t* dst = dstbase + it * 4096;
            const int k0 = it * 32;
            #pragma unroll
            for (int p = 0; p < 4; p++) {
                int row = lrow + p * 32;
                float4 w4 = *(const float4*)(W + (long)(n0 + row) * E_DIM + k0 + lkc);
                int nb8 = row >> 3;
                int laneb = (row & 7) * 4;
                int R = (row + sbq) & 3;
                uint32_t* bw = dst + ((sbq * 16 + nb8) * 32 + laneb) * 2 + fragb;
                bw[2 * ((0 + R) & 3)] = f2tf(w4.x);
                bw[2 * ((1 + R) & 3)] = f2tf(w4.y);
                bw[2 * ((2 + R) & 3)] = f2tf(w4.z);
                bw[2 * ((3 + R) & 3)] = f2tf(w4.w);
            }
        }
    }
}

// ---------------------------------------------------------------------------
// prep_score: build score stage tiles from g_Q / g_K.
// blocks 0..511: Q A-tiles (zz=b*16+h, tblk); 512..1023: K B-tiles.
// Index formulas verbatim from R12 score staging.
// ---------------------------------------------------------------------------
__global__ void __launch_bounds__(256) prep_score(
    const float* __restrict__ Q, const float* __restrict__ Kx,
    uint32_t* __restrict__ Qpre, uint32_t* __restrict__ Kpre)
{
    const int tid = threadIdx.x;
    const int bx = blockIdx.x;
    const int isK = bx >> 9;
    const int t = bx & 511;
    const int blk = t & 7;
    const int zz = t >> 3;           // b*16+h
    const int b = zz >> 4, h = zz & 15;
    const float* src = (isK ? Kx : Q) + (long)b * E_DIM + h * D_DIM;
    uint32_t* dst = (isK ? Kpre : Qpre) + (long)(zz * 8 + blk) * 8192;
    const int r0 = blk * 128;
    const int srow = tid >> 3, skc = (tid & 7) << 2;

    #pragma unroll
    for (int pr = 0; pr < 4; pr++) {
        int row = srow + pr * 32;
        int mbq = row >> 4, fragm = ((row & 15) >= 8) ? 1 : 0;
        int nb8 = row >> 3;
        int laneb = (row & 7) * 4;
        #pragma unroll
        for (int pk = 0; pk < 2; pk++) {
            int kc = skc + pk * 32;
            int sb = kc >> 3;
            int fragk2 = ((kc & 7) >= 4) ? 2 : 0;
            int fb = ((kc & 7) >= 4) ? 1 : 0;
            int R = (row + sb) & 3;
            float4 v4 = *(const float4*)(src + (long)(r0 + row) * BE + kc);
            if (!isK) {
                uint32_t* aw = dst + ((sb * 8 + mbq) * 32 + laneb) * 4 + fragk2 + fragm;
                aw[4 * ((0 + R) & 3)] = f2tf(v4.x);
                aw[4 * ((1 + R) & 3)] = f2tf(v4.y);
                aw[4 * ((2 + R) & 3)] = f2tf(v4.z);
                aw[4 * ((3 + R) & 3)] = f2tf(v4.w);
            } else {
                uint32_t* bw = dst + ((sb * 16 + nb8) * 32 + laneb) * 2 + fb;
                bw[2 * ((0 + R) & 3)] = f2tf(v4.x);
                bw[2 * ((1 + R) & 3)] = f2tf(v4.y);
                bw[2 * ((2 + R) & 3)] = f2tf(v4.z);
                bw[2 * ((3 + R) & 3)] = f2tf(v4.w);
            }
        }
    }
}

// ---------------------------------------------------------------------------
// Shared MMA mainloop fragment (reads As/Bs stage, identical to R12/R13)
// ---------------------------------------------------------------------------
#define GEMM_MAINLOOP(ACUR, BCUR)                                             \
    _Pragma("unroll")                                                         \
    for (int sb = 0; sb < 4; sb++) {                                          \
        const int sw = (g << 2) + ((tg + g + sb) & 3);                        \
        uint4 af[4];                                                          \
        uint2 bf[4];                                                          \
        _Pragma("unroll")                                                     \
        for (int mt = 0; mt < 4; mt++)                                        \
            af[mt] = *(const uint4*)((ACUR) + ((sb * 8 + wmb + mt) * 32 + sw) * 4); \
        _Pragma("unroll")                                                     \
        for (int nt = 0; nt < 4; nt++)                                        \
            bf[nt] = *(const uint2*)((BCUR) + ((sb * 16 + wnb + nt) * 32 + sw) * 2); \
        _Pragma("unroll")                                                     \
        for (int mt = 0; mt < 4; mt++)                                        \
            _Pragma("unroll")                                                 \
            for (int nt = 0; nt < 4; nt++)                                    \
                mma8(acc[mt][nt], (const uint32_t*)&af[mt], (const uint32_t*)&bf[nt]); \
    }

#define GEMM_PROLOGUE                                                         \
    extern __shared__ uint32_t dsm[];                                         \
    uint32_t* As = dsm;                                                       \
    uint32_t* Bs = dsm + 8192;                                                \
    const int tid = threadIdx.x, lane = tid & 31, wid = tid >> 5;             \
    const int wm = (wid >> 2) * 64, wn = (wid & 3) * 32;                      \
    const int wmb = wm >> 4, wnb = wn >> 3;                                   \
    const int g = lane >> 2, tg = lane & 3;                                   \
    float acc[4][4][4];                                                       \
    _Pragma("unroll")                                                         \
    for (int i = 0; i < 4; i++)                                               \
        _Pragma("unroll")                                                     \
        for (int j = 0; j < 4; j++)                                           \
            _Pragma("unroll")                                                 \
            for (int q = 0; q < 4; q++) acc[i][j][q] = 0.f;

#define GEMM_EPILOGUE(CPTR, BIASPTR, ALPHA)                                   \
    _Pragma("unroll")                                                         \
    for (int mt = 0; mt < 4; mt++) {                                          \
        int r0 = m0 + wm + mt * 16 + g;                                       \
        _Pragma("unroll")                                                     \
        for (int nt = 0; nt < 4; nt++) {                                      \
            int c = n0 + wn + nt * 8 + 2 * tg;                                \
            float2 bv = *(const float2*)((BIASPTR) + c);                      \
            float2 o0, o1;                                                    \
            o0.x = (ALPHA) * (acc[mt][nt][0] + bv.x);                         \
            o0.y = (ALPHA) * (acc[mt][nt][1] + bv.y);                         \
            o1.x = (ALPHA) * (acc[mt][nt][2] + bv.x);                         \
            o1.y = (ALPHA) * (acc[mt][nt][3] + bv.y);                         \
            *(float2*)((CPTR) + (long)r0 * E_DIM + c) = o0;                   \
            *(float2*)((CPTR) + (long)(r0 + 8) * E_DIM + c) = o1;             \
        }                                                                     \
    }

// ---------------------------------------------------------------------------
// QKV projection, copy-staging from pre-converted images.
// ---------------------------------------------------------------------------
__global__ void __launch_bounds__(256) gemm_qkv(
    const uint32_t* __restrict__ Apre, const uint32_t* __restrict__ Bpre,
    const float* __restrict__ ipb,
    float* __restrict__ Qo, float* __restrict__ Ko, float* __restrict__ Vo)
{
    GEMM_PROLOGUE
    const int m0 = blockIdx.y * 128;
    const int seg = blockIdx.x >> 3;
    const int n0 = (blockIdx.x & 7) * 128;

    const float* bias = ipb + seg * E_DIM;
    float* C = (seg == 0) ? Qo : (seg == 1) ? Ko : Vo;
    const float alpha = (seg == 0) ? 0.125f : 1.0f;

    const uint4* Ap = (const uint4*)(Apre + (long)(seg * 32 + (m0 >> 7)) * (32 * 4096));
    const uint4* Bp = (const uint4*)(Bpre + (long)(seg * 8 + (n0 >> 7)) * (32 * 4096));

    uint4 ra[4], rb[4];
    #pragma unroll
    for (int p = 0; p < 4; p++) {
        ra[p] = Ap[p * 256 + tid];
        rb[p] = Bp[p * 256 + tid];
    }
    #pragma unroll
    for (int p = 0; p < 4; p++) {
        *(uint4*)(As + (p * 256 + tid) * 4) = ra[p];
        *(uint4*)(Bs + (p * 256 + tid) * 4) = rb[p];
    }

    for (int it = 0; it < 32; it++) {
        const int cur = (it & 1) * 4096;
        __syncthreads();
        if (it < 31) {
            long base = (long)(it + 1) * 1024;
            #pragma unroll
            for (int p = 0; p < 4; p++) {
                ra[p] = Ap[base + p * 256 + tid];
                rb[p] = Bp[base + p * 256 + tid];
            }
        }
        const uint32_t* Acur = As + cur;
        const uint32_t* Bcur = Bs + cur;
        GEMM_MAINLOOP(Acur, Bcur)
        if (it < 31) {
            const int nxt = ((it + 1) & 1) * 4096;
            #pragma unroll
            for (int p = 0; p < 4; p++) {
                *(uint4*)(As + nxt + (p * 256 + tid) * 4) = ra[p];
                *(uint4*)(Bs + nxt + (p * 256 + tid) * 4) = rb[p];
            }
        }
    }

    GEMM_EPILOGUE(C, bias, alpha)
}

// ---------------------------------------------------------------------------
// Output projection: A = Ctx (runtime, f2tf scatter staging as in R13),
// B = pre-converted ow image (copy staging).
// ---------------------------------------------------------------------------
__global__ void __launch_bounds__(256) gemm_out(
    const float* __restrict__ Ain, const uint32_t* __restrict__ Bpre,
    const float* __restrict__ bias, float* __restrict__ C)
{
    GEMM_PROLOGUE
    const int m0 = blockIdx.y * 128, n0 = blockIdx.x * 128;

    const uint4* Bp = (const uint4*)(Bpre + (long)(3 * 8 + (n0 >> 7)) * (32 * 4096));

    const int lrow = tid >> 3, lkc = (tid & 7) << 2;
    const int sbq = lkc >> 3;
    const int fragk2 = ((lkc & 7) >= 4) ? 2 : 0;

    float4 pa[4];
    uint4 rb[4];
    #pragma unroll
    for (int p = 0; p < 4; p++) {
        int row = lrow + p * 32;
        pa[p] = *(const float4*)(Ain + (long)(m0 + row) * E_DIM + lkc);
        rb[p] = Bp[p * 256 + tid];
    }
    #pragma unroll
    for (int p = 0; p < 4; p++) {
        int row = lrow + p * 32;
        int mbq = row >> 4, fragm = ((row & 15) >= 8) ? 1 : 0;
        int laneb = (row & 7) * 4;
        int R = (row + sbq) & 3;
        uint32_t* aw = As + ((sbq * 8 + mbq) * 32 + laneb) * 4 + fragk2 + fragm;
        aw[4 * ((0 + R) & 3)] = f2tf(pa[p].x);
        aw[4 * ((1 + R) & 3)] = f2tf(pa[p].y);
        aw[4 * ((2 + R) & 3)] = f2tf(pa[p].z);
        aw[4 * ((3 + R) & 3)] = f2tf(pa[p].w);
        *(uint4*)(Bs + (p * 256 + tid) * 4) = rb[p];
    }

    for (int it = 0; it < 32; it++) {
        const int cur = (it & 1) * 4096;
        __syncthreads();
        if (it < 31) {
            int k0 = (it + 1) * 32;
            long base = (long)(it + 1) * 1024;
            #pragma unroll
            for (int p = 0; p < 4; p++) {
                int row = lrow + p * 32;
                pa[p] = *(const float4*)(Ain + (long)(m0 + row) * E_DIM + k0 + lkc);
                rb[p] = Bp[base + p * 256 + tid];
            }
        }
        const uint32_t* Acur = As + cur;
        const uint32_t* Bcur = Bs + cur;
        GEMM_MAINLOOP(Acur, Bcur)
        if (it < 31) {
            const int nxt = ((it + 1) & 1) * 4096;
            #pragma unroll
            for (int p = 0; p < 4; p++) {
                int row = lrow + p * 32;
                int mbq = row >> 4, fragm = ((row & 15) >= 8) ? 1 : 0;
                int laneb = (row & 7) * 4;
                int R = (row + sbq) & 3;
                uint32_t* aw = As + nxt + ((sbq * 8 + mbq) * 32 + laneb) * 4 + fragk2 + fragm;
                aw[4 * ((0 + R) & 3)] = f2tf(pa[p].x);
                aw[4 * ((1 + R) & 3)] = f2tf(pa[p].y);
                aw[4 * ((2 + R) & 3)] = f2tf(pa[p].z);
                aw[4 * ((3 + R) & 3)] = f2tf(pa[p].w);
                *(uint4*)(Bs + nxt + (p * 256 + tid) * 4) = rb[p];
            }
        }
    }

    GEMM_EPILOGUE(C, bias, 1.0f)
}

// ---------------------------------------------------------------------------
// Score kernel: staging = verbatim copy of pre-converted tiles; mainloop
// and epilogue identical to R12/R13.
// ---------------------------------------------------------------------------
#define SCORE_SMEM_BYTES (16384 * 4)

__global__ void __launch_bounds__(256) score_kernel(
    const uint32_t* __restrict__ Qpre, const uint32_t* __restrict__ Kpre,
    const float* __restrict__ amask, const int* __restrict__ pad,
    float* __restrict__ Sc)
{
    extern __shared__ uint32_t dsm[];
    uint32_t* As = dsm;                 // 8192 words
    uint32_t* Bs = dsm + 8192;          // 8192 words
    const int tid = threadIdx.x, lane = tid & 31, wid = tid >> 5;
    const int wm = (wid >> 2) * 64, wn = (wid & 3) * 32;
    const int wmb = wm >> 4, wnb = wn >> 3;
    const int t0 = blockIdx.y * 128, s0 = blockIdx.x * 128;
    const int z = blockIdx.z;
    const int b = z >> 4;

    float acc[4][4][4];
    #pragma unroll
    for (int i = 0; i < 4; i++)
        #pragma unroll
        for (int j = 0; j < 4; j++)
            #pragma unroll
            for (int q = 0; q < 4; q++) acc[i][j][q] = 0.f;

    const int g = lane >> 2, tg = lane & 3;

    // copy-stage both tiles (2048 uint4 each)
    {
        const uint4* Qp = (const uint4*)(Qpre + ((long)z * 8 + (t0 >> 7)) * 8192);
        const uint4* Kp = (const uint4*)(Kpre + ((long)z * 8 + (s0 >> 7)) * 8192);
        #pragma unroll
        for (int p = 0; p < 8; p++) {
            *(uint4*)(As + (p * 256 + tid) * 4) = Qp[p * 256 + tid];
            *(uint4*)(Bs + (p * 256 + tid) * 4) = Kp[p * 256 + tid];
        }
    }
    __syncthreads();

    #pragma unroll
    for (int sb = 0; sb < 8; sb++) {
        const int sw = (g << 2) + ((tg + g + sb) & 3);
        uint4 af[4];
        uint2 bf[4];
        #pragma unroll
        for (int mt = 0; mt < 4; mt++)
            af[mt] = *(const uint4*)(As + ((sb * 8 + wmb + mt) * 32 + sw) * 4);
        #pragma unroll
        for (int nt = 0; nt < 4; nt++)
            bf[nt] = *(const uint2*)(Bs + ((sb * 16 + wnb + nt) * 32 + sw) * 2);
        #pragma unroll
        for (int mt = 0; mt < 4; mt++)
            #pragma unroll
            for (int nt = 0; nt < 4; nt++)
                mma8(acc[mt][nt], (const uint32_t*)&af[mt], (const uint32_t*)&bf[nt]);
    }

    float* So = Sc + (long)z * T_DIM * S_DIM;
    #pragma unroll
    for (int mt = 0; mt < 4; mt++) {
        int t = t0 + wm + mt * 16 + g;
        #pragma unroll
        for (int nt = 0; nt < 4; nt++) {
            int s = s0 + wn + nt * 8 + 2 * tg;
            float p0 = pad[b * S_DIM + s]     ? -1e30f : 0.f;
            float p1 = pad[b * S_DIM + s + 1] ? -1e30f : 0.f;
            float2 a0 = *(const float2*)(amask + (long)t * S_DIM + s);
            float2 a1 = *(const float2*)(amask + (long)(t + 8) * S_DIM + s);
            float2 o0, o1;
            o0.x = acc[mt][nt][0] + a0.x + p0;
            o0.y = acc[mt][nt][1] + a0.y + p1;
            o1.x = acc[mt][nt][2] + a1.x + p0;
            o1.y = acc[mt][nt][3] + a1.y + p1;
            *(float2*)(So + (long)t * S_DIM + s) = o0;
            *(float2*)(So + (long)(t + 8) * S_DIM + s) = o1;
        }
    }
}

// ---------------------------------------------------------------------------
// Softmax + head-average (R13 verbatim)
// ---------------------------------------------------------------------------
#define SA_SMEM_BYTES (H_DIM * S_DIM * 4)   // 65536

__global__ void __launch_bounds__(512) softmax_avg(
    float* __restrict__ P, float* __restrict__ avgw)
{
    extern __shared__ float Ps[];            // [16][1024]
    const int bid = blockIdx.x;
    const int b = bid >> 10, t = bid & 1023;
    const int h = threadIdx.x >> 5, lane = threadIdx.x & 31;

    float4* p = (float4*)(P + (((long)(b * H_DIM + h) * T_DIM) + t) * S_DIM);
    float4 v[8];
    float m = -1e30f;
    #pragma unroll
    for (int i = 0; i < 8; i++) {
        v[i] = p[lane + 32 * i];
        m = fmaxf(m, fmaxf(fmaxf(v[i].x, v[i].y), fmaxf(v[i].z, v[i].w)));
    }
    #pragma unroll
    for (int o = 16; o; o >>= 1) m = fmaxf(m, __shfl_xor_sync(0xffffffffu, m, o));
    float sum = 0.f;
    #pragma unroll
    for (int i = 0; i < 8; i++) {
        v[i].x = __expf(v[i].x - m); v[i].y = __expf(v[i].y - m);
        v[i].z = __expf(v[i].z - m); v[i].w = __expf(v[i].w - m);
        sum += v[i].x + v[i].y + v[i].z + v[i].w;
    }
    #pragma unroll
    for (int o = 16; o; o >>= 1) sum += __shfl_xor_sync(0xffffffffu, sum, o);
    float inv = 1.0f / sum;
    float4* ps = (float4*)(Ps + h * S_DIM);
    #pragma unroll
    for (int i = 0; i < 8; i++) {
        v[i].x *= inv; v[i].y *= inv; v[i].z *= inv; v[i].w *= inv;
        p[lane + 32 * i] = v[i];
        ps[lane + 32 * i] = v[i];
    }
    __syncthreads();

    int s2 = threadIdx.x * 2;
    float a0 = 0.f, a1 = 0.f;
    #pragma unroll
    for (int hh = 0; hh < H_DIM; hh++) {
        float2 pv = *(const float2*)(Ps + hh * S_DIM + s2);
        a0 += pv.x; a1 += pv.y;
    }
    const float inv16 = 1.0f / H_DIM;
    *(float2*)(avgw + ((long)b * T_DIM + t) * S_DIM + s2) =
        make_float2(a0 * inv16, a1 * inv16);
}

// ---------------------------------------------------------------------------
// PV (R13 verbatim): A frag+rot layout, B simple.
// ---------------------------------------------------------------------------
#define VLDB 72
#define PV_SMEM_WORDS (2 * 4096 + 2 * PBK * VLDB)
#define PV_SMEM_BYTES (PV_SMEM_WORDS * 4)

__global__ void __launch_bounds__(256) pv_kernel(
    const float* __restrict__ Sc, const float* __restrict__ V,
    float* __restrict__ Ctx)
{
    extern __shared__ uint32_t dsm[];
    uint32_t* Asm = dsm;            // 2 stages x 4096 (frag layout)
    uint32_t* Bsm = dsm + 8192;     // [2*PBK][VLDB]
    const int tid = threadIdx.x, lane = tid & 31, wid = tid >> 5;
    const int wm = (wid >> 1) * 32, wn = (wid & 1) * 32;
    const int wmb = wm >> 4;
    const int t0 = blockIdx.x * 128;
    const int z = blockIdx.z;
    const int b = z >> 4, h = z & 15;
    const int g = lane >> 2, tg = lane & 3;
    const float* Pb = Sc + (long)z * T_DIM * S_DIM;
    const float* Vb = V + (long)b * E_DIM + h * D_DIM;

    float acc[2][4][4];
    #pragma unroll
    for (int i = 0; i < 2; i++)
        #pragma unroll
        for (int j = 0; j < 4; j++)
            #pragma unroll
            for (int q = 0; q < 4; q++) acc[i][j][q] = 0.f;

    const int arow = tid >> 3, akc = (tid & 7) << 2;
    const int asb = akc >> 3;
    const int afragk2 = ((akc & 7) >= 4) ? 2 : 0;
    const int bs_s = tid >> 4, bs_d = (tid & 15) << 2;

    float4 pa[4], pv[2];
    #pragma unroll
    for (int p = 0; p < 4; p++)
        pa[p] = *(const float4*)(Pb + (long)(t0 + arow + p * 32) * S_DIM + akc);
    #pragma unroll
    for (int p = 0; p < 2; p++)
        pv[p] = *(const float4*)(Vb + (long)(bs_s + p * 16) * BE + bs_d);

#define PV_ASTAGE(AOFF)                                                       \
    _Pragma("unroll")                                                         \
    for (int p = 0; p < 4; p++) {                                             \
        int row = arow + p * 32;                                              \
        int mbq = row >> 4, fragm = ((row & 15) >= 8) ? 1 : 0;                \
        int laneb = (row & 7) * 4;                                            \
        int R = (row + asb) & 3;                                              \
        uint32_t* aw = Asm + (AOFF) + ((asb * 8 + mbq) * 32 + laneb) * 4      \
                       + afragk2 + fragm;                                     \
        aw[4 * ((0 + R) & 3)] = f2tf(pa[p].x);                                \
        aw[4 * ((1 + R) & 3)] = f2tf(pa[p].y);                                \
        aw[4 * ((2 + R) & 3)] = f2tf(pa[p].z);                                \
        aw[4 * ((3 + R) & 3)] = f2tf(pa[p].w);                                \
    }

#define PV_BSTAGE(BROW)                                                       \
    _Pragma("unroll")                                                         \
    for (int p = 0; p < 2; p++) {                                             \
        int s = bs_s + p * 16;                                                \
        Bsm[((BROW) + s) * VLDB + bs_d + 0] = f2tf(pv[p].x);                  \
        Bsm[((BROW) + s) * VLDB + bs_d + 1] = f2tf(pv[p].y);                  \
        Bsm[((BROW) + s) * VLDB + bs_d + 2] = f2tf(pv[p].z);                  \
        Bsm[((BROW) + s) * VLDB + bs_d + 3] = f2tf(pv[p].w);                  \
    }

    PV_ASTAGE(0)
    PV_BSTAGE(0)

    for (int it = 0; it < S_DIM / PBK; it++) {
        const int curA = (it & 1) * 4096;
        const int curB = (it & 1) * PBK;
        __syncthreads();
        if (it < S_DIM / PBK - 1) {
            int k0 = (it + 1) * PBK;
            #pragma unroll
            for (int p = 0; p < 4; p++)
                pa[p] = *(const float4*)(Pb + (long)(t0 + arow + p * 32) * S_DIM + k0 + akc);
            #pragma unroll
            for (int p = 0; p < 2; p++)
                pv[p] = *(const float4*)(Vb + (long)(k0 + bs_s + p * 16) * BE + bs_d);
        }
        #pragma unroll
        for (int ks = 0; ks < PBK; ks += 8) {
            const int sb = ks >> 3;
            const int sw = (g << 2) + ((tg + g + sb) & 3);
            uint4 af[2];
            uint32_t bf[4][2];
            #pragma unroll
            for (int mt = 0; mt < 2; mt++)
                af[mt] = *(const uint4*)(Asm + curA + ((sb * 8 + wmb + mt) * 32 + sw) * 4);
            #pragma unroll
            for (int nt = 0; nt < 4; nt++) {
                int n = wn + nt * 8 + g;
                bf[nt][0] = Bsm[(curB + ks + tg) * VLDB + n];
                bf[nt][1] = Bsm[(curB + ks + tg + 4) * VLDB + n];
            }
            #pragma unroll
            for (int mt = 0; mt < 2; mt++)
                #pragma unroll
                for (int nt = 0; nt < 4; nt++)
                    mma8(acc[mt][nt], (const uint32_t*)&af[mt], bf[nt]);
        }
        if (it < S_DIM / PBK - 1) {
            PV_ASTAGE(((it + 1) & 1) * 4096)
            PV_BSTAGE(((it + 1) & 1) * PBK)
        }
    }

    #pragma unroll
    for (int mt = 0; mt < 2; mt++) {
        int t = t0 + wm + mt * 16 + g;
        #pragma unroll
        for (int nt = 0; nt < 4; nt++) {
            int d = wn + nt * 8 + 2 * tg;
            *(float2*)(Ctx + (long)t * BE + b * E_DIM + h * D_DIM + d) =
                make_float2(acc[mt][nt][0], acc[mt][nt][1]);
            *(float2*)(Ctx + (long)(t + 8) * BE + b * E_DIM + h * D_DIM + d) =
                make_float2(acc[mt][nt][2], acc[mt][nt][3]);
        }
    }
}

// ---------------------------------------------------------------------------
extern "C" void kernel_launch(void* const* d_in, const int* in_sizes, int n_in,
                              void* d_out, int out_size) {
    const float* query = (const float*)d_in[0];
    const float* key   = (const float*)d_in[1];
    const float* value = (const float*)d_in[2];
    const int*   pad   = (const int*)d_in[3];
    const float* amask = (const float*)d_in[4];
    const float* ipw   = (const float*)d_in[5];
    const float* ipb   = (const float*)d_in[6];
    const float* ow    = (const float*)d_in[7];
    const float* ob    = (const float*)d_in[8];

    float* out  = (float*)d_out;
    float* avgw = out + (long)T_DIM * B_DIM * E_DIM;

    float *Qp, *Kp, *Vp, *Cp, *Pp;
    uint32_t *QKVpre, *Wpre, *Qpre, *Kpre;
    cudaGetSymbolAddress((void**)&Qp, g_Q);
    cudaGetSymbolAddress((void**)&Kp, g_K);
    cudaGetSymbolAddress((void**)&Vp, g_V);
    cudaGetSymbolAddress((void**)&Cp, g_Ctx);
    cudaGetSymbolAddress((void**)&Pp, g_P);
    cudaGetSymbolAddress((void**)&QKVpre, g_QKVpre);
    cudaGetSymbolAddress((void**)&Wpre, g_Wpre);
    cudaGetSymbolAddress((void**)&Qpre, g_Qpre);
    cudaGetSymbolAddress((void**)&Kpre, g_Kpre);

    cudaFuncSetAttribute(gemm_qkv,
        cudaFuncAttributeMaxDynamicSharedMemorySize, GEMM_SMEM_BYTES);
    cudaFuncSetAttribute(gemm_out,
        cudaFuncAttributeMaxDynamicSharedMemorySize, GEMM_SMEM_BYTES);
    cudaFuncSetAttribute(score_kernel,
        cudaFuncAttributeMaxDynamicSharedMemorySize, SCORE_SMEM_BYTES);
    cudaFuncSetAttribute(softmax_avg,
        cudaFuncAttributeMaxDynamicSharedMemorySize, SA_SMEM_BYTES);
    cudaFuncSetAttribute(pv_kernel,
        cudaFuncAttributeMaxDynamicSharedMemorySize, PV_SMEM_BYTES);

    prep_proj<<<128, 256>>>(query, key, value, ipw, ow, QKVpre, Wpre);

    gemm_qkv<<<dim3(24, 32), 256, GEMM_SMEM_BYTES>>>(
        QKVpre, Wpre, ipb, Qp, Kp, Vp);

    prep_score<<<1024, 256>>>(Qp, Kp, Qpre, Kpre);

    score_kernel<<<dim3(8, 8, 64), 256, SCORE_SMEM_BYTES>>>(
        Qpre, Kpre, amask, pad, Pp);

    softmax_avg<<<B_DIM * T_DIM, 512, SA_SMEM_BYTES>>>(Pp, avgw);

    pv_kernel<<<dim3(8, 1, 64), 256, PV_SMEM_BYTES>>>(Pp, Vp, Cp);

    gemm_out<<<dim3(8, 32), 256, GEMM_SMEM_BYTES>>>(Cp, Wpre, ob, out);
}

// round 15
// speedup vs baseline: 1.0102x; 1.0102x over previous
#include <cuda_runtime.h>
#include <cstdint>

// Problem constants
#define T_DIM 1024
#define B_DIM 4
#define S_DIM 1024
#define E_DIM 1024
#define H_DIM 16
#define D_DIM 64
#define TB (T_DIM * B_DIM)
#define BE (B_DIM * E_DIM)

// Scratch (device globals — no allocation allowed)
__device__ float g_Q[TB * E_DIM];
__device__ float g_K[TB * E_DIM];
__device__ float g_V[TB * E_DIM];
__device__ float g_Ctx[TB * E_DIM];
__device__ float g_P[(long)B_DIM * H_DIM * T_DIM * S_DIM];   // scores -> probs (256 MB)

// ---------------------------------------------------------------------------
// tf32 helpers
// ---------------------------------------------------------------------------
__device__ __forceinline__ uint32_t f2tf(float x) {
    uint32_t r;
    asm("cvt.rna.tf32.f32 %0, %1;" : "=r"(r) : "f"(x));
    return r;
}

__device__ __forceinline__ void mma8(float* d, const uint32_t* a, const uint32_t* b) {
    asm volatile(
        "mma.sync.aligned.m16n8k8.row.col.f32.tf32.tf32.f32 "
        "{%0,%1,%2,%3}, {%4,%5,%6,%7}, {%8,%9}, {%0,%1,%2,%3};\n"
        : "+f"(d[0]), "+f"(d[1]), "+f"(d[2]), "+f"(d[3])
        : "r"(a[0]), "r"(a[1]), "r"(a[2]), "r"(a[3]), "r"(b[0]), "r"(b[1]));
}

#define PBK 32
#define LDA 132

// ---------------------------------------------------------------------------
// Fragment-interleaved layout + staging rotation (validated R9/R11/R12):
// A word = ((sb*8 + m/16)*32 + (m%8)*4 + ((k%4 + m + sb)&3))*4
//          + ((k%8)>=4)*2 + ((m%16)>=8)
// B word = ((sb*16 + n/8)*32 + (n%8)*4 + ((k%4 + n + sb)&3))*2 + ((k%8)>=4)
// Mainloop: a-frag = 1 LDS.128, b-frag = 1 LDS.64 at
//   sw = g*4 + ((tg + g + sb)&3).
// ---------------------------------------------------------------------------
#define GEMM_SMEM_WORDS 16384
#define GEMM_SMEM_BYTES (GEMM_SMEM_WORDS * 4)   // 65536

#define GEMM_STAGE(DSTA, DSTB, PA, PW)                                        \
    _Pragma("unroll")                                                         \
    for (int p = 0; p < 4; p++) {                                             \
        int row = lrow + p * 32;                                              \
        int mbq = row >> 4, fragm = ((row & 15) >= 8) ? 1 : 0;                \
        int nb8 = row >> 3;                                                   \
        int laneb = (row & 7) * 4;                                            \
        int R = (row + sbq) & 3;                                              \
        uint32_t* aw = (DSTA) + ((sbq * 8 + mbq) * 32 + laneb) * 4 + fragk2 + fragm; \
        uint32_t* bw = (DSTB) + ((sbq * 16 + nb8) * 32 + laneb) * 2 + fragb;  \
        aw[4 * ((0 + R) & 3)] = f2tf((PA)[p].x);                              \
        aw[4 * ((1 + R) & 3)] = f2tf((PA)[p].y);                              \
        aw[4 * ((2 + R) & 3)] = f2tf((PA)[p].z);                              \
        aw[4 * ((3 + R) & 3)] = f2tf((PA)[p].w);                              \
        bw[2 * ((0 + R) & 3)] = f2tf((PW)[p].x);                              \
        bw[2 * ((1 + R) & 3)] = f2tf((PW)[p].y);                              \
        bw[2 * ((2 + R) & 3)] = f2tf((PW)[p].z);                              \
        bw[2 * ((3 + R) & 3)] = f2tf((PW)[p].w);                              \
    }

#define GEMM_DB_CORE(APTR, WPTR)                                              \
    const int lrow = tid >> 3, lkc = (tid & 7) << 2;                          \
    const int sbq = lkc >> 3;                                                 \
    const int fragk2 = ((lkc & 7) >= 4) ? 2 : 0;                              \
    const int fragb  = ((lkc & 7) >= 4) ? 1 : 0;                              \
    float4 pa[4], pw[4];                                                      \
    _Pragma("unroll")                                                         \
    for (int p = 0; p < 4; p++) {                                             \
        int row = lrow + p * 32;                                              \
        pa[p] = *(const float4*)((APTR) + (long)(m0 + row) * E_DIM + lkc);    \
        pw[p] = *(const float4*)((WPTR) + (long)(n0 + row) * E_DIM + lkc);    \
    }                                                                         \
    GEMM_STAGE(As, Bs, pa, pw)                                                \
    for (int it = 0; it < E_DIM / PBK; it++) {                                \
        const int cur = (it & 1) * 4096;                                      \
        __syncthreads();                                                      \
        if (it < E_DIM / PBK - 1) {                                           \
            int k0 = (it + 1) * PBK;                                          \
            _Pragma("unroll")                                                 \
            for (int p = 0; p < 4; p++) {                                     \
                int row = lrow + p * 32;                                      \
                pa[p] = *(const float4*)((APTR) + (long)(m0 + row) * E_DIM + k0 + lkc); \
                pw[p] = *(const float4*)((WPTR) + (long)(n0 + row) * E_DIM + k0 + lkc); \
            }                                                                 \
        }                                                                     \
        const uint32_t* Acur = As + cur;                                      \
        const uint32_t* Bcur = Bs + cur;                                      \
        _Pragma("unroll")                                                     \
        for (int sb = 0; sb < 4; sb++) {                                      \
            const int sw = (g << 2) + ((tg + g + sb) & 3);                    \
            uint4 af[4];                                                      \
            uint2 bf[4];                                                      \
            _Pragma("unroll")                                                 \
            for (int mt = 0; mt < 4; mt++)                                    \
                af[mt] = *(const uint4*)(Acur + ((sb * 8 + wmb + mt) * 32 + sw) * 4); \
            _Pragma("unroll")                                                 \
            for (int nt = 0; nt < 4; nt++)                                    \
                bf[nt] = *(const uint2*)(Bcur + ((sb * 16 + wnb + nt) * 32 + sw) * 2); \
            _Pragma("unroll")                                                 \
            for (int mt = 0; mt < 4; mt++)                                    \
                _Pragma("unroll")                                             \
                for (int nt = 0; nt < 4; nt++)                                \
                    mma8(acc[mt][nt], (const uint32_t*)&af[mt], (const uint32_t*)&bf[nt]); \
        }                                                                     \
        if (it < E_DIM / PBK - 1) {                                           \
            const int nxt = ((it + 1) & 1) * 4096;                            \
            GEMM_STAGE(As + nxt, Bs + nxt, pa, pw)                            \
        }                                                                     \
    }

#define GEMM_PROLOGUE                                                         \
    extern __shared__ uint32_t dsm[];                                         \
    uint32_t* As = dsm;                                                       \
    uint32_t* Bs = dsm + 8192;                                                \
    const int tid = threadIdx.x, lane = tid & 31, wid = tid >> 5;             \
    const int wm = (wid >> 2) * 64, wn = (wid & 3) * 32;                      \
    const int wmb = wm >> 4, wnb = wn >> 3;                                   \
    const int g = lane >> 2, tg = lane & 3;                                   \
    float acc[4][4][4];                                                       \
    _Pragma("unroll")                                                         \
    for (int i = 0; i < 4; i++)                                               \
        _Pragma("unroll")                                                     \
        for (int j = 0; j < 4; j++)                                           \
            _Pragma("unroll")                                                 \
            for (int q = 0; q < 4; q++) acc[i][j][q] = 0.f;

#define GEMM_EPILOGUE(CPTR, BIASPTR, ALPHA)                                   \
    _Pragma("unroll")                                                         \
    for (int mt = 0; mt < 4; mt++) {                                          \
        int r0 = m0 + wm + mt * 16 + g;                                       \
        _Pragma("unroll")                                                     \
        for (int nt = 0; nt < 4; nt++) {                                      \
            int c = n0 + wn + nt * 8 + 2 * tg;                                \
            float2 bv = *(const float2*)((BIASPTR) + c);                      \
            float2 o0, o1;                                                    \
            o0.x = (ALPHA) * (acc[mt][nt][0] + bv.x);                         \
            o0.y = (ALPHA) * (acc[mt][nt][1] + bv.y);                         \
            o1.x = (ALPHA) * (acc[mt][nt][2] + bv.x);                         \
            o1.y = (ALPHA) * (acc[mt][nt][3] + bv.y);                         \
            *(float2*)((CPTR) + (long)r0 * E_DIM + c) = o0;                   \
            *(float2*)((CPTR) + (long)(r0 + 8) * E_DIM + c) = o1;             \
        }                                                                     \
    }

// ---------------------------------------------------------------------------
// Merged QKV projection: grid (24, 32); seg = blockIdx.x>>3 picks q/k/v.
// ---------------------------------------------------------------------------
__global__ void __launch_bounds__(256) gemm_qkv(
    const float* __restrict__ query, const float* __restrict__ key,
    const float* __restrict__ value, const float* __restrict__ ipw,
    const float* __restrict__ ipb,
    float* __restrict__ Qo, float* __restrict__ Ko, float* __restrict__ Vo)
{
    GEMM_PROLOGUE
    const int m0 = blockIdx.y * 128;
    const int seg = blockIdx.x >> 3;
    const int n0 = (blockIdx.x & 7) * 128;

    const float* A = (seg == 0) ? query : (seg == 1) ? key : value;
    const float* W = ipw + (long)seg * E_DIM * E_DIM;
    const float* bias = ipb + seg * E_DIM;
    float* C = (seg == 0) ? Qo : (seg == 1) ? Ko : Vo;
    const float alpha = (seg == 0) ? 0.125f : 1.0f;

    GEMM_DB_CORE(A, W)
    GEMM_EPILOGUE(C, bias, alpha)
}

// ---------------------------------------------------------------------------
// Output projection
// ---------------------------------------------------------------------------
__global__ void __launch_bounds__(256) gemm_out(
    const float* __restrict__ Ain, const float* __restrict__ W,
    const float* __restrict__ bias, float* __restrict__ C)
{
    GEMM_PROLOGUE
    const int m0 = blockIdx.y * 128, n0 = blockIdx.x * 128;

    GEMM_DB_CORE(Ain, W)
    GEMM_EPILOGUE(C, bias, 1.0f)
}

// ---------------------------------------------------------------------------
// Score kernel — 128(T) x 64(S) tile, warp tile 64x16 (acc 32 regs),
// frag-interleaved + rotation layout, 2 CTAs/SM for latency overlap.
// A: 8 slabs x 8 mb = 8192 w | B: 8 slabs x 8 nb8 = 4096 w -> 48KB.
// Per-element accumulation order identical to R13 (k-slabs ascending).
// ---------------------------------------------------------------------------
#define SCORE_SMEM_BYTES (12288 * 4)   // 49152

__global__ void __launch_bounds__(256, 2) score_kernel(
    const float* __restrict__ Q, const float* __restrict__ Kx,
    const float* __restrict__ amask, const int* __restrict__ pad,
    float* __restrict__ Sc)
{
    extern __shared__ uint32_t dsm[];
    uint32_t* As = dsm;                 // 8192 words
    uint32_t* Bs = dsm + 8192;          // 4096 words
    const int tid = threadIdx.x, lane = tid & 31, wid = tid >> 5;
    const int wm = (wid >> 2) * 64;     // 0 or 64
    const int wn = (wid & 3) * 16;      // 0,16,32,48
    const int wmb = wm >> 4, wnb = wn >> 3;
    const int t0 = blockIdx.y * 128, s0 = blockIdx.x * 64;
    const int z = blockIdx.z;
    const int b = z >> 4, h = z & 15;
    const int g = lane >> 2, tg = lane & 3;
    const float* Qb = Q + (long)b * E_DIM + h * D_DIM;
    const float* Kb = Kx + (long)b * E_DIM + h * D_DIM;

    float acc[4][2][4];
    #pragma unroll
    for (int i = 0; i < 4; i++)
        #pragma unroll
        for (int j = 0; j < 2; j++)
            #pragma unroll
            for (int q = 0; q < 4; q++) acc[i][j][q] = 0.f;

    const int srow = tid >> 3;            // 0..31
    const int skc = (tid & 7) << 2;       // 0..28

    // stage A (Q tile, 128 rows x K=64)
    #pragma unroll
    for (int pr = 0; pr < 4; pr++) {
        int row = srow + pr * 32;
        int mbq = row >> 4, fragm = ((row & 15) >= 8) ? 1 : 0;
        int laneb = (row & 7) * 4;
        #pragma unroll
        for (int pk = 0; pk < 2; pk++) {
            int kc = skc + pk * 32;
            int sb = kc >> 3;
            int fragk2 = ((kc & 7) >= 4) ? 2 : 0;
            int R = (row + sb) & 3;
            float4 q4 = *(const float4*)(Qb + (long)(t0 + row) * BE + kc);
            uint32_t* aw = As + ((sb * 8 + mbq) * 32 + laneb) * 4 + fragk2 + fragm;
            aw[4 * ((0 + R) & 3)] = f2tf(q4.x);
            aw[4 * ((1 + R) & 3)] = f2tf(q4.y);
            aw[4 * ((2 + R) & 3)] = f2tf(q4.z);
            aw[4 * ((3 + R) & 3)] = f2tf(q4.w);
        }
    }
    // stage B (K tile, 64 rows x K=64)
    #pragma unroll
    for (int pr = 0; pr < 2; pr++) {
        int row = srow + pr * 32;
        int nb8 = row >> 3;
        int laneb = (row & 7) * 4;
        #pragma unroll
        for (int pk = 0; pk < 2; pk++) {
            int kc = skc + pk * 32;
            int sb = kc >> 3;
            int fb = ((kc & 7) >= 4) ? 1 : 0;
            int R = (row + sb) & 3;
            float4 k4 = *(const float4*)(Kb + (long)(s0 + row) * BE + kc);
            uint32_t* bw = Bs + ((sb * 8 + nb8) * 32 + laneb) * 2 + fb;
            bw[2 * ((0 + R) & 3)] = f2tf(k4.x);
            bw[2 * ((1 + R) & 3)] = f2tf(k4.y);
            bw[2 * ((2 + R) & 3)] = f2tf(k4.z);
            bw[2 * ((3 + R) & 3)] = f2tf(k4.w);
        }
    }
    __syncthreads();

    #pragma unroll
    for (int sb = 0; sb < 8; sb++) {
        const int sw = (g << 2) + ((tg + g + sb) & 3);
        uint4 af[4];
        uint2 bf[2];
        #pragma unroll
        for (int mt = 0; mt < 4; mt++)
            af[mt] = *(const uint4*)(As + ((sb * 8 + wmb + mt) * 32 + sw) * 4);
        #pragma unroll
        for (int nt = 0; nt < 2; nt++)
            bf[nt] = *(const uint2*)(Bs + ((sb * 8 + wnb + nt) * 32 + sw) * 2);
        #pragma unroll
        for (int mt = 0; mt < 4; mt++)
            #pragma unroll
            for (int nt = 0; nt < 2; nt++)
                mma8(acc[mt][nt], (const uint32_t*)&af[mt], (const uint32_t*)&bf[nt]);
    }

    float* So = Sc + (long)z * T_DIM * S_DIM;
    #pragma unroll
    for (int mt = 0; mt < 4; mt++) {
        int t = t0 + wm + mt * 16 + g;
        #pragma unroll
        for (int nt = 0; nt < 2; nt++) {
            int s = s0 + wn + nt * 8 + 2 * tg;
            float p0 = pad[b * S_DIM + s]     ? -1e30f : 0.f;
            float p1 = pad[b * S_DIM + s + 1] ? -1e30f : 0.f;
            float2 a0 = *(const float2*)(amask + (long)t * S_DIM + s);
            float2 a1 = *(const float2*)(amask + (long)(t + 8) * S_DIM + s);
            float2 o0, o1;
            o0.x = acc[mt][nt][0] + a0.x + p0;
            o0.y = acc[mt][nt][1] + a0.y + p1;
            o1.x = acc[mt][nt][2] + a1.x + p0;
            o1.y = acc[mt][nt][3] + a1.y + p1;
            *(float2*)(So + (long)t * S_DIM + s) = o0;
            *(float2*)(So + (long)(t + 8) * S_DIM + s) = o1;
        }
    }
}

// ---------------------------------------------------------------------------
// Softmax + head-average (R13 verbatim): block = (b,t), 16 warps = 16 heads.
// ---------------------------------------------------------------------------
#define SA_SMEM_BYTES (H_DIM * S_DIM * 4)   // 65536

__global__ void __launch_bounds__(512) softmax_avg(
    float* __restrict__ P, float* __restrict__ avgw)
{
    extern __shared__ float Ps[];            // [16][1024]
    const int bid = blockIdx.x;
    const int b = bid >> 10, t = bid & 1023;
    const int h = threadIdx.x >> 5, lane = threadIdx.x & 31;

    float4* p = (float4*)(P + (((long)(b * H_DIM + h) * T_DIM) + t) * S_DIM);
    float4 v[8];
    float m = -1e30f;
    #pragma unroll
    for (int i = 0; i < 8; i++) {
        v[i] = p[lane + 32 * i];
        m = fmaxf(m, fmaxf(fmaxf(v[i].x, v[i].y), fmaxf(v[i].z, v[i].w)));
    }
    #pragma unroll
    for (int o = 16; o; o >>= 1) m = fmaxf(m, __shfl_xor_sync(0xffffffffu, m, o));
    float sum = 0.f;
    #pragma unroll
    for (int i = 0; i < 8; i++) {
        v[i].x = __expf(v[i].x - m); v[i].y = __expf(v[i].y - m);
        v[i].z = __expf(v[i].z - m); v[i].w = __expf(v[i].w - m);
        sum += v[i].x + v[i].y + v[i].z + v[i].w;
    }
    #pragma unroll
    for (int o = 16; o; o >>= 1) sum += __shfl_xor_sync(0xffffffffu, sum, o);
    float inv = 1.0f / sum;
    float4* ps = (float4*)(Ps + h * S_DIM);
    #pragma unroll
    for (int i = 0; i < 8; i++) {
        v[i].x *= inv; v[i].y *= inv; v[i].z *= inv; v[i].w *= inv;
        p[lane + 32 * i] = v[i];
        ps[lane + 32 * i] = v[i];
    }
    __syncthreads();

    int s2 = threadIdx.x * 2;
    float a0 = 0.f, a1 = 0.f;
    #pragma unroll
    for (int hh = 0; hh < H_DIM; hh++) {
        float2 pv = *(const float2*)(Ps + hh * S_DIM + s2);
        a0 += pv.x; a1 += pv.y;
    }
    const float inv16 = 1.0f / H_DIM;
    *(float2*)(avgw + ((long)b * T_DIM + t) * S_DIM + s2) =
        make_float2(a0 * inv16, a1 * inv16);
}

// ---------------------------------------------------------------------------
// PV (R13 verbatim): A (P matrix) frag+rot layout, B simple.
// ---------------------------------------------------------------------------
#define VLDB 72
#define PV_SMEM_WORDS (2 * 4096 + 2 * PBK * VLDB)
#define PV_SMEM_BYTES (PV_SMEM_WORDS * 4)

__global__ void __launch_bounds__(256) pv_kernel(
    const float* __restrict__ Sc, const float* __restrict__ V,
    float* __restrict__ Ctx)
{
    extern __shared__ uint32_t dsm[];
    uint32_t* Asm = dsm;            // 2 stages x 4096 (frag layout)
    uint32_t* Bsm = dsm + 8192;     // [2*PBK][VLDB]
    const int tid = threadIdx.x, lane = tid & 31, wid = tid >> 5;
    const int wm = (wid >> 1) * 32, wn = (wid & 1) * 32;
    const int wmb = wm >> 4;
    const int t0 = blockIdx.x * 128;
    const int z = blockIdx.z;
    const int b = z >> 4, h = z & 15;
    const int g = lane >> 2, tg = lane & 3;
    const float* Pb = Sc + (long)z * T_DIM * S_DIM;
    const float* Vb = V + (long)b * E_DIM + h * D_DIM;

    float acc[2][4][4];
    #pragma unroll
    for (int i = 0; i < 2; i++)
        #pragma unroll
        for (int j = 0; j < 4; j++)
            #pragma unroll
            for (int q = 0; q < 4; q++) acc[i][j][q] = 0.f;

    const int arow = tid >> 3, akc = (tid & 7) << 2;
    const int asb = akc >> 3;
    const int afragk2 = ((akc & 7) >= 4) ? 2 : 0;
    const int bs_s = tid >> 4, bs_d = (tid & 15) << 2;

    float4 pa[4], pv[2];
    #pragma unroll
    for (int p = 0; p < 4; p++)
        pa[p] = *(const float4*)(Pb + (long)(t0 + arow + p * 32) * S_DIM + akc);
    #pragma unroll
    for (int p = 0; p < 2; p++)
        pv[p] = *(const float4*)(Vb + (long)(bs_s + p * 16) * BE + bs_d);

#define PV_ASTAGE(AOFF)                                                       \
    _Pragma("unroll")                                                         \
    for (int p = 0; p < 4; p++) {                                             \
        int row = arow + p * 32;                                              \
        int mbq = row >> 4, fragm = ((row & 15) >= 8) ? 1 : 0;                \
        int laneb = (row & 7) * 4;                                            \
        int R = (row + asb) & 3;                                              \
        uint32_t* aw = Asm + (AOFF) + ((asb * 8 + mbq) * 32 + laneb) * 4      \
                       + afragk2 + fragm;                                     \
        aw[4 * ((0 + R) & 3)] = f2tf(pa[p].x);                                \
        aw[4 * ((1 + R) & 3)] = f2tf(pa[p].y);                                \
        aw[4 * ((2 + R) & 3)] = f2tf(pa[p].z);                                \
        aw[4 * ((3 + R) & 3)] = f2tf(pa[p].w);                                \
    }

#define PV_BSTAGE(BROW)                                                       \
    _Pragma("unroll")                                                         \
    for (int p = 0; p < 2; p++) {                                             \
        int s = bs_s + p * 16;                                                \
        Bsm[((BROW) + s) * VLDB + bs_d + 0] = f2tf(pv[p].x);                  \
        Bsm[((BROW) + s) * VLDB + bs_d + 1] = f2tf(pv[p].y);                  \
        Bsm[((BROW) + s) * VLDB + bs_d + 2] = f2tf(pv[p].z);                  \
        Bsm[((BROW) + s) * VLDB + bs_d + 3] = f2tf(pv[p].w);                  \
    }

    PV_ASTAGE(0)
    PV_BSTAGE(0)

    for (int it = 0; it < S_DIM / PBK; it++) {
        const int curA = (it & 1) * 4096;
        const int curB = (it & 1) * PBK;
        __syncthreads();
        if (it < S_DIM / PBK - 1) {
            int k0 = (it + 1) * PBK;
            #pragma unroll
            for (int p = 0; p < 4; p++)
                pa[p] = *(const float4*)(Pb + (long)(t0 + arow + p * 32) * S_DIM + k0 + akc);
            #pragma unroll
            for (int p = 0; p < 2; p++)
                pv[p] = *(const float4*)(Vb + (long)(k0 + bs_s + p * 16) * BE + bs_d);
        }
        #pragma unroll
        for (int ks = 0; ks < PBK; ks += 8) {
            const int sb = ks >> 3;
            const int sw = (g << 2) + ((tg + g + sb) & 3);
            uint4 af[2];
            uint32_t bf[4][2];
            #pragma unroll
            for (int mt = 0; mt < 2; mt++)
                af[mt] = *(const uint4*)(Asm + curA + ((sb * 8 + wmb + mt) * 32 + sw) * 4);
            #pragma unroll
            for (int nt = 0; nt < 4; nt++) {
                int n = wn + nt * 8 + g;
                bf[nt][0] = Bsm[(curB + ks + tg) * VLDB + n];
                bf[nt][1] = Bsm[(curB + ks + tg + 4) * VLDB + n];
            }
            #pragma unroll
            for (int mt = 0; mt < 2; mt++)
                #pragma unroll
                for (int nt = 0; nt < 4; nt++)
                    mma8(acc[mt][nt], (const uint32_t*)&af[mt], bf[nt]);
        }
        if (it < S_DIM / PBK - 1) {
            PV_ASTAGE(((it + 1) & 1) * 4096)
            PV_BSTAGE(((it + 1) & 1) * PBK)
        }
    }

    #pragma unroll
    for (int mt = 0; mt < 2; mt++) {
        int t = t0 + wm + mt * 16 + g;
        #pragma unroll
        for (int nt = 0; nt < 4; nt++) {
            int d = wn + nt * 8 + 2 * tg;
            *(float2*)(Ctx + (long)t * BE + b * E_DIM + h * D_DIM + d) =
                make_float2(acc[mt][nt][0], acc[mt][nt][1]);
            *(float2*)(Ctx + (long)(t + 8) * BE + b * E_DIM + h * D_DIM + d) =
                make_float2(acc[mt][nt][2], acc[mt][nt][3]);
        }
    }
}

// ---------------------------------------------------------------------------
extern "C" void kernel_launch(void* const* d_in, const int* in_sizes, int n_in,
                              void* d_out, int out_size) {
    const float* query = (const float*)d_in[0];
    const float* key   = (const float*)d_in[1];
    const float* value = (const float*)d_in[2];
    const int*   pad   = (const int*)d_in[3];
    const float* amask = (const float*)d_in[4];
    const float* ipw   = (const float*)d_in[5];
    const float* ipb   = (const float*)d_in[6];
    const float* ow    = (const float*)d_in[7];
    const float* ob    = (const float*)d_in[8];

    float* out  = (float*)d_out;
    float* avgw = out + (long)T_DIM * B_DIM * E_DIM;

    float *Qp, *Kp, *Vp, *Cp, *Pp;
    cudaGetSymbolAddress((void**)&Qp, g_Q);
    cudaGetSymbolAddress((void**)&Kp, g_K);
    cudaGetSymbolAddress((void**)&Vp, g_V);
    cudaGetSymbolAddress((void**)&Cp, g_Ctx);
    cudaGetSymbolAddress((void**)&Pp, g_P);

    cudaFuncSetAttribute(gemm_qkv,
        cudaFuncAttributeMaxDynamicSharedMemorySize, GEMM_SMEM_BYTES);
    cudaFuncSetAttribute(gemm_out,
        cudaFuncAttributeMaxDynamicSharedMemorySize, GEMM_SMEM_BYTES);
    cudaFuncSetAttribute(score_kernel,
        cudaFuncAttributeMaxDynamicSharedMemorySize, SCORE_SMEM_BYTES);
    cudaFuncSetAttribute(softmax_avg,
        cudaFuncAttributeMaxDynamicSharedMemorySize, SA_SMEM_BYTES);
    cudaFuncSetAttribute(pv_kernel,
        cudaFuncAttributeMaxDynamicSharedMemorySize, PV_SMEM_BYTES);

    gemm_qkv<<<dim3(24, 32), 256, GEMM_SMEM_BYTES>>>(
        query, key, value, ipw, ipb, Qp, Kp, Vp);

    score_kernel<<<dim3(16, 8, 64), 256, SCORE_SMEM_BYTES>>>(
        Qp, Kp, amask, pad, Pp);

    softmax_avg<<<B_DIM * T_DIM, 512, SA_SMEM_BYTES>>>(Pp, avgw);

    pv_kernel<<<dim3(8, 1, 64), 256, PV_SMEM_BYTES>>>(Pp, Vp, Cp);

    gemm_out<<<dim3(8, 32), 256, GEMM_SMEM_BYTES>>>(Cp, ow, ob, out);
}

// round 16
// speedup vs baseline: 1.0735x; 1.0627x over previous
#include <cuda_runtime.h>
#include <cstdint>

// Problem constants
#define T_DIM 1024
#define B_DIM 4
#define S_DIM 1024
#define E_DIM 1024
#define H_DIM 16
#define D_DIM 64
#define TB (T_DIM * B_DIM)
#define BE (B_DIM * E_DIM)

// Scratch (device globals — no allocation allowed)
__device__ float g_Q[TB * E_DIM];
__device__ float g_K[TB * E_DIM];
__device__ float g_V[TB * E_DIM];
__device__ float g_Ctx[TB * E_DIM];
__device__ float g_P[(long)B_DIM * H_DIM * T_DIM * S_DIM];   // scores -> probs (256 MB)

// ---------------------------------------------------------------------------
// tf32 helpers
// ---------------------------------------------------------------------------
__device__ __forceinline__ uint32_t f2tf(float x) {
    uint32_t r;
    asm("cvt.rna.tf32.f32 %0, %1;" : "=r"(r) : "f"(x));
    return r;
}

__device__ __forceinline__ void mma8(float* d, const uint32_t* a, const uint32_t* b) {
    asm volatile(
        "mma.sync.aligned.m16n8k8.row.col.f32.tf32.tf32.f32 "
        "{%0,%1,%2,%3}, {%4,%5,%6,%7}, {%8,%9}, {%0,%1,%2,%3};\n"
        : "+f"(d[0]), "+f"(d[1]), "+f"(d[2]), "+f"(d[3])
        : "r"(a[0]), "r"(a[1]), "r"(a[2]), "r"(a[3]), "r"(b[0]), "r"(b[1]));
}

#define PBK 32
#define LDA 132

// ---------------------------------------------------------------------------
// Fragment-interleaved layout + staging rotation (validated R9/R11/R12):
// A word = ((sb*8 + m/16)*32 + (m%8)*4 + ((k%4 + m + sb)&3))*4
//          + ((k%8)>=4)*2 + ((m%16)>=8)
// B word = ((sb*16 + n/8)*32 + (n%8)*4 + ((k%4 + n + sb)&3))*2 + ((k%8)>=4)
// Mainloop: a-frag = 1 LDS.128, b-frag = 1 LDS.64 at
//   sw = g*4 + ((tg + g + sb)&3).
// ---------------------------------------------------------------------------
#define GEMM_SMEM_WORDS 16384
#define GEMM_SMEM_BYTES (GEMM_SMEM_WORDS * 4)   // 65536

#define GEMM_STAGE(DSTA, DSTB, PA, PW)                                        \
    _Pragma("unroll")                                                         \
    for (int p = 0; p < 4; p++) {                                             \
        int row = lrow + p * 32;                                              \
        int mbq = row >> 4, fragm = ((row & 15) >= 8) ? 1 : 0;                \
        int nb8 = row >> 3;                                                   \
        int laneb = (row & 7) * 4;                                            \
        int R = (row + sbq) & 3;                                              \
        uint32_t* aw = (DSTA) + ((sbq * 8 + mbq) * 32 + laneb) * 4 + fragk2 + fragm; \
        uint32_t* bw = (DSTB) + ((sbq * 16 + nb8) * 32 + laneb) * 2 + fragb;  \
        aw[4 * ((0 + R) & 3)] = f2tf((PA)[p].x);                              \
        aw[4 * ((1 + R) & 3)] = f2tf((PA)[p].y);                              \
        aw[4 * ((2 + R) & 3)] = f2tf((PA)[p].z);                              \
        aw[4 * ((3 + R) & 3)] = f2tf((PA)[p].w);                              \
        bw[2 * ((0 + R) & 3)] = f2tf((PW)[p].x);                              \
        bw[2 * ((1 + R) & 3)] = f2tf((PW)[p].y);                              \
        bw[2 * ((2 + R) & 3)] = f2tf((PW)[p].z);                              \
        bw[2 * ((3 + R) & 3)] = f2tf((PW)[p].w);                              \
    }

#define GEMM_DB_CORE(APTR, WPTR)                                              \
    const int lrow = tid >> 3, lkc = (tid & 7) << 2;                          \
    const int sbq = lkc >> 3;                                                 \
    const int fragk2 = ((lkc & 7) >= 4) ? 2 : 0;                              \
    const int fragb  = ((lkc & 7) >= 4) ? 1 : 0;                              \
    float4 pa[4], pw[4];                                                      \
    _Pragma("unroll")                                                         \
    for (int p = 0; p < 4; p++) {                                             \
        int row = lrow + p * 32;                                              \
        pa[p] = *(const float4*)((APTR) + (long)(m0 + row) * E_DIM + lkc);    \
        pw[p] = *(const float4*)((WPTR) + (long)(n0 + row) * E_DIM + lkc);    \
    }                                                                         \
    GEMM_STAGE(As, Bs, pa, pw)                                                \
    for (int it = 0; it < E_DIM / PBK; it++) {                                \
        const int cur = (it & 1) * 4096;                                      \
        __syncthreads();                                                      \
        if (it < E_DIM / PBK - 1) {                                           \
            int k0 = (it + 1) * PBK;                                          \
            _Pragma("unroll")                                                 \
            for (int p = 0; p < 4; p++) {                                     \
                int row = lrow + p * 32;                                      \
                pa[p] = *(const float4*)((APTR) + (long)(m0 + row) * E_DIM + k0 + lkc); \
                pw[p] = *(const float4*)((WPTR) + (long)(n0 + row) * E_DIM + k0 + lkc); \
            }                                                                 \
        }                                                                     \
        const uint32_t* Acur = As + cur;                                      \
        const uint32_t* Bcur = Bs + cur;                                      \
        _Pragma("unroll")                                                     \
        for (int sb = 0; sb < 4; sb++) {                                      \
            const int sw = (g << 2) + ((tg + g + sb) & 3);                    \
            uint4 af[4];                                                      \
            uint2 bf[4];                                                      \
            _Pragma("unroll")                                                 \
            for (int mt = 0; mt < 4; mt++)                                    \
                af[mt] = *(const uint4*)(Acur + ((sb * 8 + wmb + mt) * 32 + sw) * 4); \
            _Pragma("unroll")                                                 \
            for (int nt = 0; nt < 4; nt++)                                    \
                bf[nt] = *(const uint2*)(Bcur + ((sb * 16 + wnb + nt) * 32 + sw) * 2); \
            _Pragma("unroll")                                                 \
            for (int mt = 0; mt < 4; mt++)                                    \
                _Pragma("unroll")                                             \
                for (int nt = 0; nt < 4; nt++)                                \
                    mma8(acc[mt][nt], (const uint32_t*)&af[mt], (const uint32_t*)&bf[nt]); \
        }                                                                     \
        if (it < E_DIM / PBK - 1) {                                           \
            const int nxt = ((it + 1) & 1) * 4096;                            \
            GEMM_STAGE(As + nxt, Bs + nxt, pa, pw)                            \
        }                                                                     \
    }

#define GEMM_PROLOGUE                                                         \
    extern __shared__ uint32_t dsm[];                                         \
    uint32_t* As = dsm;                                                       \
    uint32_t* Bs = dsm + 8192;                                                \
    const int tid = threadIdx.x, lane = tid & 31, wid = tid >> 5;             \
    const int wm = (wid >> 2) * 64, wn = (wid & 3) * 32;                      \
    const int wmb = wm >> 4, wnb = wn >> 3;                                   \
    const int g = lane >> 2, tg = lane & 3;                                   \
    float acc[4][4][4];                                                       \
    _Pragma("unroll")                                                         \
    for (int i = 0; i < 4; i++)                                               \
        _Pragma("unroll")                                                     \
        for (int j = 0; j < 4; j++)                                           \
            _Pragma("unroll")                                                 \
            for (int q = 0; q < 4; q++) acc[i][j][q] = 0.f;

#define GEMM_EPILOGUE(CPTR, BIASPTR, ALPHA)                                   \
    _Pragma("unroll")                                                         \
    for (int mt = 0; mt < 4; mt++) {                                          \
        int r0 = m0 + wm + mt * 16 + g;                                       \
        _Pragma("unroll")                                                     \
        for (int nt = 0; nt < 4; nt++) {                                      \
            int c = n0 + wn + nt * 8 + 2 * tg;                                \
            float2 bv = *(const float2*)((BIASPTR) + c);                      \
            float2 o0, o1;                                                    \
            o0.x = (ALPHA) * (acc[mt][nt][0] + bv.x);                         \
            o0.y = (ALPHA) * (acc[mt][nt][1] + bv.y);                         \
            o1.x = (ALPHA) * (acc[mt][nt][2] + bv.x);                         \
            o1.y = (ALPHA) * (acc[mt][nt][3] + bv.y);                         \
            *(float2*)((CPTR) + (long)r0 * E_DIM + c) = o0;                   \
            *(float2*)((CPTR) + (long)(r0 + 8) * E_DIM + c) = o1;             \
        }                                                                     \
    }

// ---------------------------------------------------------------------------
// Merged QKV projection: grid (24, 32); seg = blockIdx.x>>3 picks q/k/v.
// ---------------------------------------------------------------------------
__global__ void __launch_bounds__(256) gemm_qkv(
    const float* __restrict__ query, const float* __restrict__ key,
    const float* __restrict__ value, const float* __restrict__ ipw,
    const float* __restrict__ ipb,
    float* __restrict__ Qo, float* __restrict__ Ko, float* __restrict__ Vo)
{
    GEMM_PROLOGUE
    const int m0 = blockIdx.y * 128;
    const int seg = blockIdx.x >> 3;
    const int n0 = (blockIdx.x & 7) * 128;

    const float* A = (seg == 0) ? query : (seg == 1) ? key : value;
    const float* W = ipw + (long)seg * E_DIM * E_DIM;
    const float* bias = ipb + seg * E_DIM;
    float* C = (seg == 0) ? Qo : (seg == 1) ? Ko : Vo;
    const float alpha = (seg == 0) ? 0.125f : 1.0f;

    GEMM_DB_CORE(A, W)
    GEMM_EPILOGUE(C, bias, alpha)
}

// ---------------------------------------------------------------------------
// Output projection
// ---------------------------------------------------------------------------
__global__ void __launch_bounds__(256) gemm_out(
    const float* __restrict__ Ain, const float* __restrict__ W,
    const float* __restrict__ bias, float* __restrict__ C)
{
    GEMM_PROLOGUE
    const int m0 = blockIdx.y * 128, n0 = blockIdx.x * 128;

    GEMM_DB_CORE(Ain, W)
    GEMM_EPILOGUE(C, bias, 1.0f)
}

// ---------------------------------------------------------------------------
// Score kernel — frag-interleaved + rotation (R12/R13 structure), but the
// epilogue now stores RAW scores (mask application moved to softmax_avg).
// ---------------------------------------------------------------------------
#define SCORE_SMEM_BYTES (16384 * 4)

__global__ void __launch_bounds__(256) score_kernel(
    const float* __restrict__ Q, const float* __restrict__ Kx,
    float* __restrict__ Sc)
{
    extern __shared__ uint32_t dsm[];
    uint32_t* As = dsm;                 // 8192 words
    uint32_t* Bs = dsm + 8192;          // 8192 words
    const int tid = threadIdx.x, lane = tid & 31, wid = tid >> 5;
    const int wm = (wid >> 2) * 64, wn = (wid & 3) * 32;
    const int wmb = wm >> 4, wnb = wn >> 3;
    const int t0 = blockIdx.y * 128, s0 = blockIdx.x * 128;
    const int z = blockIdx.z;
    const int b = z >> 4, h = z & 15;
    const int g = lane >> 2, tg = lane & 3;
    const float* Qb = Q + (long)b * E_DIM + h * D_DIM;
    const float* Kb = Kx + (long)b * E_DIM + h * D_DIM;

    float acc[4][4][4];
    #pragma unroll
    for (int i = 0; i < 4; i++)
        #pragma unroll
        for (int j = 0; j < 4; j++)
            #pragma unroll
            for (int q = 0; q < 4; q++) acc[i][j][q] = 0.f;

    {
        const int srow = tid >> 3;            // 0..31 (+pr*32)
        const int skc = (tid & 7) << 2;       // 0,4,...,28 (+pk*32)
        #pragma unroll
        for (int pr = 0; pr < 4; pr++) {
            int row = srow + pr * 32;
            int mbq = row >> 4, fragm = ((row & 15) >= 8) ? 1 : 0;
            int nb8 = row >> 3;
            int laneb = (row & 7) * 4;
            #pragma unroll
            for (int pk = 0; pk < 2; pk++) {
                int kc = skc + pk * 32;
                int sb = kc >> 3;
                int fragk2 = ((kc & 7) >= 4) ? 2 : 0;
                int fb = ((kc & 7) >= 4) ? 1 : 0;
                int R = (row + sb) & 3;
                float4 q4 = *(const float4*)(Qb + (long)(t0 + row) * BE + kc);
                float4 k4 = *(const float4*)(Kb + (long)(s0 + row) * BE + kc);
                uint32_t* aw = As + ((sb * 8 + mbq) * 32 + laneb) * 4 + fragk2 + fragm;
                uint32_t* bw = Bs + ((sb * 16 + nb8) * 32 + laneb) * 2 + fb;
                aw[4 * ((0 + R) & 3)] = f2tf(q4.x);
                aw[4 * ((1 + R) & 3)] = f2tf(q4.y);
                aw[4 * ((2 + R) & 3)] = f2tf(q4.z);
                aw[4 * ((3 + R) & 3)] = f2tf(q4.w);
                bw[2 * ((0 + R) & 3)] = f2tf(k4.x);
                bw[2 * ((1 + R) & 3)] = f2tf(k4.y);
                bw[2 * ((2 + R) & 3)] = f2tf(k4.z);
                bw[2 * ((3 + R) & 3)] = f2tf(k4.w);
            }
        }
    }
    __syncthreads();

    #pragma unroll
    for (int sb = 0; sb < 8; sb++) {
        const int sw = (g << 2) + ((tg + g + sb) & 3);
        uint4 af[4];
        uint2 bf[4];
        #pragma unroll
        for (int mt = 0; mt < 4; mt++)
            af[mt] = *(const uint4*)(As + ((sb * 8 + wmb + mt) * 32 + sw) * 4);
        #pragma unroll
        for (int nt = 0; nt < 4; nt++)
            bf[nt] = *(const uint2*)(Bs + ((sb * 16 + wnb + nt) * 32 + sw) * 2);
        #pragma unroll
        for (int mt = 0; mt < 4; mt++)
            #pragma unroll
            for (int nt = 0; nt < 4; nt++)
                mma8(acc[mt][nt], (const uint32_t*)&af[mt], (const uint32_t*)&bf[nt]);
    }

    // store raw scores (masks applied later in softmax_avg)
    float* So = Sc + (long)z * T_DIM * S_DIM;
    #pragma unroll
    for (int mt = 0; mt < 4; mt++) {
        int t = t0 + wm + mt * 16 + g;
        #pragma unroll
        for (int nt = 0; nt < 4; nt++) {
            int s = s0 + wn + nt * 8 + 2 * tg;
            *(float2*)(So + (long)t * S_DIM + s) =
                make_float2(acc[mt][nt][0], acc[mt][nt][1]);
            *(float2*)(So + (long)(t + 8) * S_DIM + s) =
                make_float2(acc[mt][nt][2], acc[mt][nt][3]);
        }
    }
}

// ---------------------------------------------------------------------------
// Softmax + head-average; now also applies attn_mask + padding mask at load
// (same fp32 association order as the old score epilogue: (s + a) + p).
// block = (b,t), 16 warps = 16 heads.
// ---------------------------------------------------------------------------
#define SA_SMEM_BYTES (H_DIM * S_DIM * 4)   // 65536

__global__ void __launch_bounds__(512) softmax_avg(
    float* __restrict__ P, const float* __restrict__ amask,
    const int* __restrict__ pad, float* __restrict__ avgw)
{
    extern __shared__ float Ps[];            // [16][1024]
    const int bid = blockIdx.x;
    const int b = bid >> 10, t = bid & 1023;
    const int h = threadIdx.x >> 5, lane = threadIdx.x & 31;

    float4* p = (float4*)(P + (((long)(b * H_DIM + h) * T_DIM) + t) * S_DIM);
    const float4* am = (const float4*)(amask + (long)t * S_DIM);
    const int4*  pd  = (const int4*)(pad + b * S_DIM);
    float4 v[8];
    float m = -1e30f;
    #pragma unroll
    for (int i = 0; i < 8; i++) {
        float4 sv = p[lane + 32 * i];
        float4 av = am[lane + 32 * i];
        int4 p4 = pd[lane + 32 * i];
        sv.x = sv.x + av.x + (p4.x ? -1e30f : 0.f);
        sv.y = sv.y + av.y + (p4.y ? -1e30f : 0.f);
        sv.z = sv.z + av.z + (p4.z ? -1e30f : 0.f);
        sv.w = sv.w + av.w + (p4.w ? -1e30f : 0.f);
        v[i] = sv;
        m = fmaxf(m, fmaxf(fmaxf(sv.x, sv.y), fmaxf(sv.z, sv.w)));
    }
    #pragma unroll
    for (int o = 16; o; o >>= 1) m = fmaxf(m, __shfl_xor_sync(0xffffffffu, m, o));
    float sum = 0.f;
    #pragma unroll
    for (int i = 0; i < 8; i++) {
        v[i].x = __expf(v[i].x - m); v[i].y = __expf(v[i].y - m);
        v[i].z = __expf(v[i].z - m); v[i].w = __expf(v[i].w - m);
        sum += v[i].x + v[i].y + v[i].z + v[i].w;
    }
    #pragma unroll
    for (int o = 16; o; o >>= 1) sum += __shfl_xor_sync(0xffffffffu, sum, o);
    float inv = 1.0f / sum;
    float4* ps = (float4*)(Ps + h * S_DIM);
    #pragma unroll
    for (int i = 0; i < 8; i++) {
        v[i].x *= inv; v[i].y *= inv; v[i].z *= inv; v[i].w *= inv;
        p[lane + 32 * i] = v[i];
        ps[lane + 32 * i] = v[i];
    }
    __syncthreads();

    int s2 = threadIdx.x * 2;
    float a0 = 0.f, a1 = 0.f;
    #pragma unroll
    for (int hh = 0; hh < H_DIM; hh++) {
        float2 pv = *(const float2*)(Ps + hh * S_DIM + s2);
        a0 += pv.x; a1 += pv.y;
    }
    const float inv16 = 1.0f / H_DIM;
    *(float2*)(avgw + ((long)b * T_DIM + t) * S_DIM + s2) =
        make_float2(a0 * inv16, a1 * inv16);
}

// ---------------------------------------------------------------------------
// PV (R13 verbatim): A (P matrix) frag+rot layout, B simple.
// ---------------------------------------------------------------------------
#define VLDB 72
#define PV_SMEM_WORDS (2 * 4096 + 2 * PBK * VLDB)
#define PV_SMEM_BYTES (PV_SMEM_WORDS * 4)

__global__ void __launch_bounds__(256) pv_kernel(
    const float* __restrict__ Sc, const float* __restrict__ V,
    float* __restrict__ Ctx)
{
    extern __shared__ uint32_t dsm[];
    uint32_t* Asm = dsm;            // 2 stages x 4096 (frag layout)
    uint32_t* Bsm = dsm + 8192;     // [2*PBK][VLDB]
    const int tid = threadIdx.x, lane = tid & 31, wid = tid >> 5;
    const int wm = (wid >> 1) * 32, wn = (wid & 1) * 32;
    const int wmb = wm >> 4;
    const int t0 = blockIdx.x * 128;
    const int z = blockIdx.z;
    const int b = z >> 4, h = z & 15;
    const int g = lane >> 2, tg = lane & 3;
    const float* Pb = Sc + (long)z * T_DIM * S_DIM;
    const float* Vb = V + (long)b * E_DIM + h * D_DIM;

    float acc[2][4][4];
    #pragma unroll
    for (int i = 0; i < 2; i++)
        #pragma unroll
        for (int j = 0; j < 4; j++)
            #pragma unroll
            for (int q = 0; q < 4; q++) acc[i][j][q] = 0.f;

    const int arow = tid >> 3, akc = (tid & 7) << 2;
    const int asb = akc >> 3;
    const int afragk2 = ((akc & 7) >= 4) ? 2 : 0;
    const int bs_s = tid >> 4, bs_d = (tid & 15) << 2;

    float4 pa[4], pv[2];
    #pragma unroll
    for (int p = 0; p < 4; p++)
        pa[p] = *(const float4*)(Pb + (long)(t0 + arow + p * 32) * S_DIM + akc);
    #pragma unroll
    for (int p = 0; p < 2; p++)
        pv[p] = *(const float4*)(Vb + (long)(bs_s + p * 16) * BE + bs_d);

#define PV_ASTAGE(AOFF)                                                       \
    _Pragma("unroll")                                                         \
    for (int p = 0; p < 4; p++) {                                             \
        int row = arow + p * 32;                                              \
        int mbq = row >> 4, fragm = ((row & 15) >= 8) ? 1 : 0;                \
        int laneb = (row & 7) * 4;                                            \
        int R = (row + asb) & 3;                                              \
        uint32_t* aw = Asm + (AOFF) + ((asb * 8 + mbq) * 32 + laneb) * 4      \
                       + afragk2 + fragm;                                     \
        aw[4 * ((0 + R) & 3)] = f2tf(pa[p].x);                                \
        aw[4 * ((1 + R) & 3)] = f2tf(pa[p].y);                                \
        aw[4 * ((2 + R) & 3)] = f2tf(pa[p].z);                                \
        aw[4 * ((3 + R) & 3)] = f2tf(pa[p].w);                                \
    }

#define PV_BSTAGE(BROW)                                                       \
    _Pragma("unroll")                                                         \
    for (int p = 0; p < 2; p++) {                                             \
        int s = bs_s + p * 16;                                                \
        Bsm[((BROW) + s) * VLDB + bs_d + 0] = f2tf(pv[p].x);                  \
        Bsm[((BROW) + s) * VLDB + bs_d + 1] = f2tf(pv[p].y);                  \
        Bsm[((BROW) + s) * VLDB + bs_d + 2] = f2tf(pv[p].z);                  \
        Bsm[((BROW) + s) * VLDB + bs_d + 3] = f2tf(pv[p].w);                  \
    }

    PV_ASTAGE(0)
    PV_BSTAGE(0)

    for (int it = 0; it < S_DIM / PBK; it++) {
        const int curA = (it & 1) * 4096;
        const int curB = (it & 1) * PBK;
        __syncthreads();
        if (it < S_DIM / PBK - 1) {
            int k0 = (it + 1) * PBK;
            #pragma unroll
            for (int p = 0; p < 4; p++)
                pa[p] = *(const float4*)(Pb + (long)(t0 + arow + p * 32) * S_DIM + k0 + akc);
            #pragma unroll
            for (int p = 0; p < 2; p++)
                pv[p] = *(const float4*)(Vb + (long)(k0 + bs_s + p * 16) * BE + bs_d);
        }
        #pragma unroll
        for (int ks = 0; ks < PBK; ks += 8) {
            const int sb = ks >> 3;
            const int sw = (g << 2) + ((tg + g + sb) & 3);
            uint4 af[2];
            uint32_t bf[4][2];
            #pragma unroll
            for (int mt = 0; mt < 2; mt++)
                af[mt] = *(const uint4*)(Asm + curA + ((sb * 8 + wmb + mt) * 32 + sw) * 4);
            #pragma unroll
            for (int nt = 0; nt < 4; nt++) {
                int n = wn + nt * 8 + g;
                bf[nt][0] = Bsm[(curB + ks + tg) * VLDB + n];
                bf[nt][1] = Bsm[(curB + ks + tg + 4) * VLDB + n];
            }
            #pragma unroll
            for (int mt = 0; mt < 2; mt++)
                #pragma unroll
                for (int nt = 0; nt < 4; nt++)
                    mma8(acc[mt][nt], (const uint32_t*)&af[mt], bf[nt]);
        }
        if (it < S_DIM / PBK - 1) {
            PV_ASTAGE(((it + 1) & 1) * 4096)
            PV_BSTAGE(((it + 1) & 1) * PBK)
        }
    }

    #pragma unroll
    for (int mt = 0; mt < 2; mt++) {
        int t = t0 + wm + mt * 16 + g;
        #pragma unroll
        for (int nt = 0; nt < 4; nt++) {
            int d = wn + nt * 8 + 2 * tg;
            *(float2*)(Ctx + (long)t * BE + b * E_DIM + h * D_DIM + d) =
                make_float2(acc[mt][nt][0], acc[mt][nt][1]);
            *(float2*)(Ctx + (long)(t + 8) * BE + b * E_DIM + h * D_DIM + d) =
                make_float2(acc[mt][nt][2], acc[mt][nt][3]);
        }
    }
}

// ---------------------------------------------------------------------------
extern "C" void kernel_launch(void* const* d_in, const int* in_sizes, int n_in,
                              void* d_out, int out_size) {
    const float* query = (const float*)d_in[0];
    const float* key   = (const float*)d_in[1];
    const float* value = (const float*)d_in[2];
    const int*   pad   = (const int*)d_in[3];
    const float* amask = (const float*)d_in[4];
    const float* ipw   = (const float*)d_in[5];
    const float* ipb   = (const float*)d_in[6];
    const float* ow    = (const float*)d_in[7];
    const float* ob    = (const float*)d_in[8];

    float* out  = (float*)d_out;
    float* avgw = out + (long)T_DIM * B_DIM * E_DIM;

    float *Qp, *Kp, *Vp, *Cp, *Pp;
    cudaGetSymbolAddress((void**)&Qp, g_Q);
    cudaGetSymbolAddress((void**)&Kp, g_K);
    cudaGetSymbolAddress((void**)&Vp, g_V);
    cudaGetSymbolAddress((void**)&Cp, g_Ctx);
    cudaGetSymbolAddress((void**)&Pp, g_P);

    cudaFuncSetAttribute(gemm_qkv,
        cudaFuncAttributeMaxDynamicSharedMemorySize, GEMM_SMEM_BYTES);
    cudaFuncSetAttribute(gemm_out,
        cudaFuncAttributeMaxDynamicSharedMemorySize, GEMM_SMEM_BYTES);
    cudaFuncSetAttribute(score_kernel,
        cudaFuncAttributeMaxDynamicSharedMemorySize, SCORE_SMEM_BYTES);
    cudaFuncSetAttribute(softmax_avg,
        cudaFuncAttributeMaxDynamicSharedMemorySize, SA_SMEM_BYTES);
    cudaFuncSetAttribute(pv_kernel,
        cudaFuncAttributeMaxDynamicSharedMemorySize, PV_SMEM_BYTES);

    gemm_qkv<<<dim3(24, 32), 256, GEMM_SMEM_BYTES>>>(
        query, key, value, ipw, ipb, Qp, Kp, Vp);

    score_kernel<<<dim3(8, 8, 64), 256, SCORE_SMEM_BYTES>>>(Qp, Kp, Pp);

    softmax_avg<<<B_DIM * T_DIM, 512, SA_SMEM_BYTES>>>(Pp, amask, pad, avgw);

    pv_kernel<<<dim3(8, 1, 64), 256, PV_SMEM_BYTES>>>(Pp, Vp, Cp);

    gemm_out<<<dim3(8, 32), 256, GEMM_SMEM_BYTES>>>(Cp, ow, ob, out);
}

// round 17
// speedup vs baseline: 1.0787x; 1.0048x over previous
#include <cuda_runtime.h>
#include <cstdint>

// Problem constants
#define T_DIM 1024
#define B_DIM 4
#define S_DIM 1024
#define E_DIM 1024
#define H_DIM 16
#define D_DIM 64
#define TB (T_DIM * B_DIM)
#define BE (B_DIM * E_DIM)

// Scratch (device globals — no allocation allowed)
// g_Q/g_K/g_V/g_Ctx hold tf32 BITS (uint32) produced by the upstream kernel.
__device__ uint32_t g_Q[TB * E_DIM];
__device__ uint32_t g_K[TB * E_DIM];
__device__ uint32_t g_V[TB * E_DIM];
__device__ uint32_t g_Ctx[TB * E_DIM];
// g_P: raw fp32 scores (score_kernel) -> overwritten with tf32 prob bits (softmax_avg)
__device__ float g_P[(long)B_DIM * H_DIM * T_DIM * S_DIM];   // 256 MB

// ---------------------------------------------------------------------------
// tf32 helpers
// ---------------------------------------------------------------------------
__device__ __forceinline__ uint32_t f2tf(float x) {
    uint32_t r;
    asm("cvt.rna.tf32.f32 %0, %1;" : "=r"(r) : "f"(x));
    return r;
}

__device__ __forceinline__ void mma8(float* d, const uint32_t* a, const uint32_t* b) {
    asm volatile(
        "mma.sync.aligned.m16n8k8.row.col.f32.tf32.tf32.f32 "
        "{%0,%1,%2,%3}, {%4,%5,%6,%7}, {%8,%9}, {%0,%1,%2,%3};\n"
        : "+f"(d[0]), "+f"(d[1]), "+f"(d[2]), "+f"(d[3])
        : "r"(a[0]), "r"(a[1]), "r"(a[2]), "r"(a[3]), "r"(b[0]), "r"(b[1]));
}

#define PBK 32
#define LDA 132

// ---------------------------------------------------------------------------
// Fragment-interleaved layout + staging rotation (validated R9/R11/R12).
// ---------------------------------------------------------------------------
#define GEMM_SMEM_WORDS 16384
#define GEMM_SMEM_BYTES (GEMM_SMEM_WORDS * 4)   // 65536

#define GEMM_STAGE(DSTA, DSTB, PA, PW)                                        \
    _Pragma("unroll")                                                         \
    for (int p = 0; p < 4; p++) {                                             \
        int row = lrow + p * 32;                                              \
        int mbq = row >> 4, fragm = ((row & 15) >= 8) ? 1 : 0;                \
        int nb8 = row >> 3;                                                   \
        int laneb = (row & 7) * 4;                                            \
        int R = (row + sbq) & 3;                                              \
        uint32_t* aw = (DSTA) + ((sbq * 8 + mbq) * 32 + laneb) * 4 + fragk2 + fragm; \
        uint32_t* bw = (DSTB) + ((sbq * 16 + nb8) * 32 + laneb) * 2 + fragb;  \
        aw[4 * ((0 + R) & 3)] = f2tf((PA)[p].x);                              \
        aw[4 * ((1 + R) & 3)] = f2tf((PA)[p].y);                              \
        aw[4 * ((2 + R) & 3)] = f2tf((PA)[p].z);                              \
        aw[4 * ((3 + R) & 3)] = f2tf((PA)[p].w);                              \
        bw[2 * ((0 + R) & 3)] = f2tf((PW)[p].x);                              \
        bw[2 * ((1 + R) & 3)] = f2tf((PW)[p].y);                              \
        bw[2 * ((2 + R) & 3)] = f2tf((PW)[p].z);                              \
        bw[2 * ((3 + R) & 3)] = f2tf((PW)[p].w);                              \
    }

#define GEMM_DB_CORE(APTR, WPTR)                                              \
    const int lrow = tid >> 3, lkc = (tid & 7) << 2;                          \
    const int sbq = lkc >> 3;                                                 \
    const int fragk2 = ((lkc & 7) >= 4) ? 2 : 0;                              \
    const int fragb  = ((lkc & 7) >= 4) ? 1 : 0;                              \
    float4 pa[4], pw[4];                                                      \
    _Pragma("unroll")                                                         \
    for (int p = 0; p < 4; p++) {                                             \
        int row = lrow + p * 32;                                              \
        pa[p] = *(const float4*)((APTR) + (long)(m0 + row) * E_DIM + lkc);    \
        pw[p] = *(const float4*)((WPTR) + (long)(n0 + row) * E_DIM + lkc);    \
    }                                                                         \
    GEMM_STAGE(As, Bs, pa, pw)                                                \
    for (int it = 0; it < E_DIM / PBK; it++) {                                \
        const int cur = (it & 1) * 4096;                                      \
        __syncthreads();                                                      \
        if (it < E_DIM / PBK - 1) {                                           \
            int k0 = (it + 1) * PBK;                                          \
            _Pragma("unroll")                                                 \
            for (int p = 0; p < 4; p++) {                                     \
                int row = lrow + p * 32;                                      \
                pa[p] = *(const float4*)((APTR) + (long)(m0 + row) * E_DIM + k0 + lkc); \
                pw[p] = *(const float4*)((WPTR) + (long)(n0 + row) * E_DIM + k0 + lkc); \
            }                                                                 \
        }                                                                     \
        const uint32_t* Acur = As + cur;                                      \
        const uint32_t* Bcur = Bs + cur;                                      \
        _Pragma("unroll")                                                     \
        for (int sb = 0; sb < 4; sb++) {                                      \
            const int sw = (g << 2) + ((tg + g + sb) & 3);                    \
            uint4 af[4];                                                      \
            uint2 bf[4];                                                      \
            _Pragma("unroll")                                                 \
            for (int mt = 0; mt < 4; mt++)                                    \
                af[mt] = *(const uint4*)(Acur + ((sb * 8 + wmb + mt) * 32 + sw) * 4); \
            _Pragma("unroll")                                                 \
            for (int nt = 0; nt < 4; nt++)                                    \
                bf[nt] = *(const uint2*)(Bcur + ((sb * 16 + wnb + nt) * 32 + sw) * 2); \
            _Pragma("unroll")                                                 \
            for (int mt = 0; mt < 4; mt++)                                    \
                _Pragma("unroll")                                             \
                for (int nt = 0; nt < 4; nt++)                                \
                    mma8(acc[mt][nt], (const uint32_t*)&af[mt], (const uint32_t*)&bf[nt]); \
        }                                                                     \
        if (it < E_DIM / PBK - 1) {                                           \
            const int nxt = ((it + 1) & 1) * 4096;                            \
            GEMM_STAGE(As + nxt, Bs + nxt, pa, pw)                            \
        }                                                                     \
    }

#define GEMM_PROLOGUE                                                         \
    extern __shared__ uint32_t dsm[];                                         \
    uint32_t* As = dsm;                                                       \
    uint32_t* Bs = dsm + 8192;                                                \
    const int tid = threadIdx.x, lane = tid & 31, wid = tid >> 5;             \
    const int wm = (wid >> 2) * 64, wn = (wid & 3) * 32;                      \
    const int wmb = wm >> 4, wnb = wn >> 3;                                   \
    const int g = lane >> 2, tg = lane & 3;                                   \
    float acc[4][4][4];                                                       \
    _Pragma("unroll")                                                         \
    for (int i = 0; i < 4; i++)                                               \
        _Pragma("unroll")                                                     \
        for (int j = 0; j < 4; j++)                                           \
            _Pragma("unroll")                                                 \
            for (int q = 0; q < 4; q++) acc[i][j][q] = 0.f;

// ---------------------------------------------------------------------------
// Merged QKV projection — epilogue stores tf32 BITS (consumers only ever
// convert these values, so this is bit-identical downstream).
// ---------------------------------------------------------------------------
__global__ void __launch_bounds__(256) gemm_qkv(
    const float* __restrict__ query, const float* __restrict__ key,
    const float* __restrict__ value, const float* __restrict__ ipw,
    const float* __restrict__ ipb,
    uint32_t* __restrict__ Qo, uint32_t* __restrict__ Ko, uint32_t* __restrict__ Vo)
{
    GEMM_PROLOGUE
    const int m0 = blockIdx.y * 128;
    const int seg = blockIdx.x >> 3;
    const int n0 = (blockIdx.x & 7) * 128;

    const float* A = (seg == 0) ? query : (seg == 1) ? key : value;
    const float* W = ipw + (long)seg * E_DIM * E_DIM;
    const float* bias = ipb + seg * E_DIM;
    uint32_t* C = (seg == 0) ? Qo : (seg == 1) ? Ko : Vo;
    const float alpha = (seg == 0) ? 0.125f : 1.0f;

    GEMM_DB_CORE(A, W)

    #pragma unroll
    for (int mt = 0; mt < 4; mt++) {
        int r0 = m0 + wm + mt * 16 + g;
        #pragma unroll
        for (int nt = 0; nt < 4; nt++) {
            int c = n0 + wn + nt * 8 + 2 * tg;
            float2 bv = *(const float2*)(bias + c);
            uint2 o0, o1;
            o0.x = f2tf(alpha * (acc[mt][nt][0] + bv.x));
            o0.y = f2tf(alpha * (acc[mt][nt][1] + bv.y));
            o1.x = f2tf(alpha * (acc[mt][nt][2] + bv.x));
            o1.y = f2tf(alpha * (acc[mt][nt][3] + bv.y));
            *(uint2*)(C + (long)r0 * E_DIM + c) = o0;
            *(uint2*)(C + (long)(r0 + 8) * E_DIM + c) = o1;
        }
    }
}

// ---------------------------------------------------------------------------
// Output projection: A = Ctx (tf32 bits -> copy-scatter staging, no CVT),
// B = ow (fp32, convert at stage). Final out stays fp32.
// ---------------------------------------------------------------------------
__global__ void __launch_bounds__(256) gemm_out(
    const uint32_t* __restrict__ Ain, const float* __restrict__ W,
    const float* __restrict__ bias, float* __restrict__ C)
{
    GEMM_PROLOGUE
    const int m0 = blockIdx.y * 128, n0 = blockIdx.x * 128;

    const int lrow = tid >> 3, lkc = (tid & 7) << 2;
    const int sbq = lkc >> 3;
    const int fragk2 = ((lkc & 7) >= 4) ? 2 : 0;
    const int fragb  = ((lkc & 7) >= 4) ? 1 : 0;

    uint4 pa[4];
    float4 pw[4];
    #pragma unroll
    for (int p = 0; p < 4; p++) {
        int row = lrow + p * 32;
        pa[p] = *(const uint4*)(Ain + (long)(m0 + row) * E_DIM + lkc);
        pw[p] = *(const float4*)(W + (long)(n0 + row) * E_DIM + lkc);
    }

#define GOUT_STAGE(DSTA, DSTB)                                                \
    _Pragma("unroll")                                                         \
    for (int p = 0; p < 4; p++) {                                             \
        int row = lrow + p * 32;                                              \
        int mbq = row >> 4, fragm = ((row & 15) >= 8) ? 1 : 0;                \
        int nb8 = row >> 3;                                                   \
        int laneb = (row & 7) * 4;                                            \
        int R = (row + sbq) & 3;                                              \
        uint32_t* aw = (DSTA) + ((sbq * 8 + mbq) * 32 + laneb) * 4 + fragk2 + fragm; \
        uint32_t* bw = (DSTB) + ((sbq * 16 + nb8) * 32 + laneb) * 2 + fragb;  \
        aw[4 * ((0 + R) & 3)] = pa[p].x;                                      \
        aw[4 * ((1 + R) & 3)] = pa[p].y;                                      \
        aw[4 * ((2 + R) & 3)] = pa[p].z;                                      \
        aw[4 * ((3 + R) & 3)] = pa[p].w;                                      \
        bw[2 * ((0 + R) & 3)] = f2tf(pw[p].x);                                \
        bw[2 * ((1 + R) & 3)] = f2tf(pw[p].y);                                \
        bw[2 * ((2 + R) & 3)] = f2tf(pw[p].z);                                \
        bw[2 * ((3 + R) & 3)] = f2tf(pw[p].w);                                \
    }

    GOUT_STAGE(As, Bs)

    for (int it = 0; it < E_DIM / PBK; it++) {
        const int cur = (it & 1) * 4096;
        __syncthreads();
        if (it < E_DIM / PBK - 1) {
            int k0 = (it + 1) * PBK;
            #pragma unroll
            for (int p = 0; p < 4; p++) {
                int row = lrow + p * 32;
                pa[p] = *(const uint4*)(Ain + (long)(m0 + row) * E_DIM + k0 + lkc);
                pw[p] = *(const float4*)(W + (long)(n0 + row) * E_DIM + k0 + lkc);
            }
        }
        const uint32_t* Acur = As + cur;
        const uint32_t* Bcur = Bs + cur;
        #pragma unroll
        for (int sb = 0; sb < 4; sb++) {
            const int sw = (g << 2) + ((tg + g + sb) & 3);
            uint4 af[4];
            uint2 bf[4];
            #pragma unroll
            for (int mt = 0; mt < 4; mt++)
                af[mt] = *(const uint4*)(Acur + ((sb * 8 + wmb + mt) * 32 + sw) * 4);
            #pragma unroll
            for (int nt = 0; nt < 4; nt++)
                bf[nt] = *(const uint2*)(Bcur + ((sb * 16 + wnb + nt) * 32 + sw) * 2);
            #pragma unroll
            for (int mt = 0; mt < 4; mt++)
                #pragma unroll
                for (int nt = 0; nt < 4; nt++)
                    mma8(acc[mt][nt], (const uint32_t*)&af[mt], (const uint32_t*)&bf[nt]);
        }
        if (it < E_DIM / PBK - 1) {
            const int nxt = ((it + 1) & 1) * 4096;
            uint32_t* Anx = As + nxt;
            uint32_t* Bnx = Bs + nxt;
            GOUT_STAGE(Anx, Bnx)
        }
    }

    #pragma unroll
    for (int mt = 0; mt < 4; mt++) {
        int r0 = m0 + wm + mt * 16 + g;
        #pragma unroll
        for (int nt = 0; nt < 4; nt++) {
            int c = n0 + wn + nt * 8 + 2 * tg;
            float2 bv = *(const float2*)(bias + c);
            float2 o0, o1;
            o0.x = acc[mt][nt][0] + bv.x;
            o0.y = acc[mt][nt][1] + bv.y;
            o1.x = acc[mt][nt][2] + bv.x;
            o1.y = acc[mt][nt][3] + bv.y;
            *(float2*)(C + (long)r0 * E_DIM + c) = o0;
            *(float2*)(C + (long)(r0 + 8) * E_DIM + c) = o1;
        }
    }
}

// ---------------------------------------------------------------------------
// Score kernel — Q/K arrive as tf32 bits; staging is pure copy-scatter.
// Stores RAW fp32 scores (masks applied in softmax_avg).
// ---------------------------------------------------------------------------
#define SCORE_SMEM_BYTES (16384 * 4)

__global__ void __launch_bounds__(256) score_kernel(
    const uint32_t* __restrict__ Q, const uint32_t* __restrict__ Kx,
    float* __restrict__ Sc)
{
    extern __shared__ uint32_t dsm[];
    uint32_t* As = dsm;                 // 8192 words
    uint32_t* Bs = dsm + 8192;          // 8192 words
    const int tid = threadIdx.x, lane = tid & 31, wid = tid >> 5;
    const int wm = (wid >> 2) * 64, wn = (wid & 3) * 32;
    const int wmb = wm >> 4, wnb = wn >> 3;
    const int t0 = blockIdx.y * 128, s0 = blockIdx.x * 128;
    const int z = blockIdx.z;
    const int b = z >> 4, h = z & 15;
    const int g = lane >> 2, tg = lane & 3;
    const uint32_t* Qb = Q + (long)b * E_DIM + h * D_DIM;
    const uint32_t* Kb = Kx + (long)b * E_DIM + h * D_DIM;

    float acc[4][4][4];
    #pragma unroll
    for (int i = 0; i < 4; i++)
        #pragma unroll
        for (int j = 0; j < 4; j++)
            #pragma unroll
            for (int q = 0; q < 4; q++) acc[i][j][q] = 0.f;

    {
        const int srow = tid >> 3;            // 0..31 (+pr*32)
        const int skc = (tid & 7) << 2;       // 0,4,...,28 (+pk*32)
        #pragma unroll
        for (int pr = 0; pr < 4; pr++) {
            int row = srow + pr * 32;
            int mbq = row >> 4, fragm = ((row & 15) >= 8) ? 1 : 0;
            int nb8 = row >> 3;
            int laneb = (row & 7) * 4;
            #pragma unroll
            for (int pk = 0; pk < 2; pk++) {
                int kc = skc + pk * 32;
                int sb = kc >> 3;
                int fragk2 = ((kc & 7) >= 4) ? 2 : 0;
                int fb = ((kc & 7) >= 4) ? 1 : 0;
                int R = (row + sb) & 3;
                uint4 q4 = *(const uint4*)(Qb + (long)(t0 + row) * BE + kc);
                uint4 k4 = *(const uint4*)(Kb + (long)(s0 + row) * BE + kc);
                uint32_t* aw = As + ((sb * 8 + mbq) * 32 + laneb) * 4 + fragk2 + fragm;
                uint32_t* bw = Bs + ((sb * 16 + nb8) * 32 + laneb) * 2 + fb;
                aw[4 * ((0 + R) & 3)] = q4.x;
                aw[4 * ((1 + R) & 3)] = q4.y;
                aw[4 * ((2 + R) & 3)] = q4.z;
                aw[4 * ((3 + R) & 3)] = q4.w;
                bw[2 * ((0 + R) & 3)] = k4.x;
                bw[2 * ((1 + R) & 3)] = k4.y;
                bw[2 * ((2 + R) & 3)] = k4.z;
                bw[2 * ((3 + R) & 3)] = k4.w;
            }
        }
    }
    __syncthreads();

    #pragma unroll
    for (int sb = 0; sb < 8; sb++) {
        const int sw = (g << 2) + ((tg + g + sb) & 3);
        uint4 af[4];
        uint2 bf[4];
        #pragma unroll
        for (int mt = 0; mt < 4; mt++)
            af[mt] = *(const uint4*)(As + ((sb * 8 + wmb + mt) * 32 + sw) * 4);
        #pragma unroll
        for (int nt = 0; nt < 4; nt++)
            bf[nt] = *(const uint2*)(Bs + ((sb * 16 + wnb + nt) * 32 + sw) * 2);
        #pragma unroll
        for (int mt = 0; mt < 4; mt++)
            #pragma unroll
            for (int nt = 0; nt < 4; nt++)
                mma8(acc[mt][nt], (const uint32_t*)&af[mt], (const uint32_t*)&bf[nt]);
    }

    float* So = Sc + (long)z * T_DIM * S_DIM;
    #pragma unroll
    for (int mt = 0; mt < 4; mt++) {
        int t = t0 + wm + mt * 16 + g;
        #pragma unroll
        for (int nt = 0; nt < 4; nt++) {
            int s = s0 + wn + nt * 8 + 2 * tg;
            *(float2*)(So + (long)t * S_DIM + s) =
                make_float2(acc[mt][nt][0], acc[mt][nt][1]);
            *(float2*)(So + (long)(t + 8) * S_DIM + s) =
                make_float2(acc[mt][nt][2], acc[mt][nt][3]);
        }
    }
}

// ---------------------------------------------------------------------------
// Softmax + head-average; applies masks at load (fp32, order (s+a)+p),
// computes avgw from fp32 p, then writes P as tf32 BITS for pv.
// ---------------------------------------------------------------------------
#define SA_SMEM_BYTES (H_DIM * S_DIM * 4)   // 65536

__global__ void __launch_bounds__(512) softmax_avg(
    float* __restrict__ P, const float* __restrict__ amask,
    const int* __restrict__ pad, float* __restrict__ avgw)
{
    extern __shared__ float Ps[];            // [16][1024]
    const int bid = blockIdx.x;
    const int b = bid >> 10, t = bid & 1023;
    const int h = threadIdx.x >> 5, lane = threadIdx.x & 31;

    float4* p = (float4*)(P + (((long)(b * H_DIM + h) * T_DIM) + t) * S_DIM);
    const float4* am = (const float4*)(amask + (long)t * S_DIM);
    const int4*  pd  = (const int4*)(pad + b * S_DIM);
    float4 v[8];
    float m = -1e30f;
    #pragma unroll
    for (int i = 0; i < 8; i++) {
        float4 sv = p[lane + 32 * i];
        float4 av = am[lane + 32 * i];
        int4 p4 = pd[lane + 32 * i];
        sv.x = sv.x + av.x + (p4.x ? -1e30f : 0.f);
        sv.y = sv.y + av.y + (p4.y ? -1e30f : 0.f);
        sv.z = sv.z + av.z + (p4.z ? -1e30f : 0.f);
        sv.w = sv.w + av.w + (p4.w ? -1e30f : 0.f);
        v[i] = sv;
        m = fmaxf(m, fmaxf(fmaxf(sv.x, sv.y), fmaxf(sv.z, sv.w)));
    }
    #pragma unroll
    for (int o = 16; o; o >>= 1) m = fmaxf(m, __shfl_xor_sync(0xffffffffu, m, o));
    float sum = 0.f;
    #pragma unroll
    for (int i = 0; i < 8; i++) {
        v[i].x = __expf(v[i].x - m); v[i].y = __expf(v[i].y - m);
        v[i].z = __expf(v[i].z - m); v[i].w = __expf(v[i].w - m);
        sum += v[i].x + v[i].y + v[i].z + v[i].w;
    }
    #pragma unroll
    for (int o = 16; o; o >>= 1) sum += __shfl_xor_sync(0xffffffffu, sum, o);
    float inv = 1.0f / sum;
    float4* ps = (float4*)(Ps + h * S_DIM);
    uint4* pu = (uint4*)p;
    #pragma unroll
    for (int i = 0; i < 8; i++) {
        float4 pv4;
        pv4.x = v[i].x * inv; pv4.y = v[i].y * inv;
        pv4.z = v[i].z * inv; pv4.w = v[i].w * inv;
        ps[lane + 32 * i] = pv4;           // fp32 for avgw reduction
        uint4 u;
        u.x = f2tf(pv4.x); u.y = f2tf(pv4.y);
        u.z = f2tf(pv4.z); u.w = f2tf(pv4.w);
        pu[lane + 32 * i] = u;             // tf32 bits for pv_kernel
    }
    __syncthreads();

    int s2 = threadIdx.x * 2;
    float a0 = 0.f, a1 = 0.f;
    #pragma unroll
    for (int hh = 0; hh < H_DIM; hh++) {
        float2 pv2 = *(const float2*)(Ps + hh * S_DIM + s2);
        a0 += pv2.x; a1 += pv2.y;
    }
    const float inv16 = 1.0f / H_DIM;
    *(float2*)(avgw + ((long)b * T_DIM + t) * S_DIM + s2) =
        make_float2(a0 * inv16, a1 * inv16);
}

// ---------------------------------------------------------------------------
// PV: A (P tf32 bits) frag+rot layout copy-scatter; B (V tf32 bits) simple
// copy; epilogue stores Ctx as tf32 bits for gemm_out.
// ---------------------------------------------------------------------------
#define VLDB 72
#define PV_SMEM_WORDS (2 * 4096 + 2 * PBK * VLDB)
#define PV_SMEM_BYTES (PV_SMEM_WORDS * 4)

__global__ void __launch_bounds__(256) pv_kernel(
    const uint32_t* __restrict__ Sc, const uint32_t* __restrict__ V,
    uint32_t* __restrict__ Ctx)
{
    extern __shared__ uint32_t dsm[];
    uint32_t* Asm = dsm;            // 2 stages x 4096 (frag layout)
    uint32_t* Bsm = dsm + 8192;     // [2*PBK][VLDB]
    const int tid = threadIdx.x, lane = tid & 31, wid = tid >> 5;
    const int wm = (wid >> 1) * 32, wn = (wid & 1) * 32;
    const int wmb = wm >> 4;
    const int t0 = blockIdx.x * 128;
    const int z = blockIdx.z;
    const int b = z >> 4, h = z & 15;
    const int g = lane >> 2, tg = lane & 3;
    const uint32_t* Pb = Sc + (long)z * T_DIM * S_DIM;
    const uint32_t* Vb = V + (long)b * E_DIM + h * D_DIM;

    float acc[2][4][4];
    #pragma unroll
    for (int i = 0; i < 2; i++)
        #pragma unroll
        for (int j = 0; j < 4; j++)
            #pragma unroll
            for (int q = 0; q < 4; q++) acc[i][j][q] = 0.f;

    const int arow = tid >> 3, akc = (tid & 7) << 2;
    const int asb = akc >> 3;
    const int afragk2 = ((akc & 7) >= 4) ? 2 : 0;
    const int bs_s = tid >> 4, bs_d = (tid & 15) << 2;

    uint4 pa[4], pv[2];
    #pragma unroll
    for (int p = 0; p < 4; p++)
        pa[p] = *(const uint4*)(Pb + (long)(t0 + arow + p * 32) * S_DIM + akc);
    #pragma unroll
    for (int p = 0; p < 2; p++)
        pv[p] = *(const uint4*)(Vb + (long)(bs_s + p * 16) * BE + bs_d);

#define PV_ASTAGE(AOFF)                                                       \
    _Pragma("unroll")                                                         \
    for (int p = 0; p < 4; p++) {                                             \
        int row = arow + p * 32;                                              \
        int mbq = row >> 4, fragm = ((row & 15) >= 8) ? 1 : 0;                \
        int laneb = (row & 7) * 4;                                            \
        int R = (row + asb) & 3;                                              \
        uint32_t* aw = Asm + (AOFF) + ((asb * 8 + mbq) * 32 + laneb) * 4      \
                       + afragk2 + fragm;                                     \
        aw[4 * ((0 + R) & 3)] = pa[p].x;                                      \
        aw[4 * ((1 + R) & 3)] = pa[p].y;                                      \
        aw[4 * ((2 + R) & 3)] = pa[p].z;                                      \
        aw[4 * ((3 + R) & 3)] = pa[p].w;                                      \
    }

#define PV_BSTAGE(BROW)                                                       \
    _Pragma("unroll")                                                         \
    for (int p = 0; p < 2; p++) {                                             \
        int s = bs_s + p * 16;                                                \
        Bsm[((BROW) + s) * VLDB + bs_d + 0] = pv[p].x;                        \
        Bsm[((BROW) + s) * VLDB + bs_d + 1] = pv[p].y;                        \
        Bsm[((BROW) + s) * VLDB + bs_d + 2] = pv[p].z;                        \
        Bsm[((BROW) + s) * VLDB + bs_d + 3] = pv[p].w;                        \
    }

    PV_ASTAGE(0)
    PV_BSTAGE(0)

    for (int it = 0; it < S_DIM / PBK; it++) {
        const int curA = (it & 1) * 4096;
        const int curB = (it & 1) * PBK;
        __syncthreads();
        if (it < S_DIM / PBK - 1) {
            int k0 = (it + 1) * PBK;
            #pragma unroll
            for (int p = 0; p < 4; p++)
                pa[p] = *(const uint4*)(Pb + (long)(t0 + arow + p * 32) * S_DIM + k0 + akc);
            #pragma unroll
            for (int p = 0; p < 2; p++)
                pv[p] = *(const uint4*)(Vb + (long)(k0 + bs_s + p * 16) * BE + bs_d);
        }
        #pragma unroll
        for (int ks = 0; ks < PBK; ks += 8) {
            const int sb = ks >> 3;
            const int sw = (g << 2) + ((tg + g + sb) & 3);
            uint4 af[2];
            uint32_t bf[4][2];
            #pragma unroll
            for (int mt = 0; mt < 2; mt++)
                af[mt] = *(const uint4*)(Asm + curA + ((sb * 8 + wmb + mt) * 32 + sw) * 4);
            #pragma unroll
            for (int nt = 0; nt < 4; nt++) {
                int n = wn + nt * 8 + g;
                bf[nt][0] = Bsm[(curB + ks + tg) * VLDB + n];
                bf[nt][1] = Bsm[(curB + ks + tg + 4) * VLDB + n];
            }
            #pragma unroll
            for (int mt = 0; mt < 2; mt++)
                #pragma unroll
                for (int nt = 0; nt < 4; nt++)
                    mma8(acc[mt][nt], (const uint32_t*)&af[mt], bf[nt]);
        }
        if (it < S_DIM / PBK - 1) {
            PV_ASTAGE(((it + 1) & 1) * 4096)
            PV_BSTAGE(((it + 1) & 1) * PBK)
        }
    }

    #pragma unroll
    for (int mt = 0; mt < 2; mt++) {
        int t = t0 + wm + mt * 16 + g;
        #pragma unroll
        for (int nt = 0; nt < 4; nt++) {
            int d = wn + nt * 8 + 2 * tg;
            uint2 o0, o1;
            o0.x = f2tf(acc[mt][nt][0]); o0.y = f2tf(acc[mt][nt][1]);
            o1.x = f2tf(acc[mt][nt][2]); o1.y = f2tf(acc[mt][nt][3]);
            *(uint2*)(Ctx + (long)t * BE + b * E_DIM + h * D_DIM + d) = o0;
            *(uint2*)(Ctx + (long)(t + 8) * BE + b * E_DIM + h * D_DIM + d) = o1;
        }
    }
}

// ---------------------------------------------------------------------------
extern "C" void kernel_launch(void* const* d_in, const int* in_sizes, int n_in,
                              void* d_out, int out_size) {
    const float* query = (const float*)d_in[0];
    const float* key   = (const float*)d_in[1];
    const float* value = (const float*)d_in[2];
    const int*   pad   = (const int*)d_in[3];
    const float* amask = (const float*)d_in[4];
    const float* ipw   = (const float*)d_in[5];
    const float* ipb   = (const float*)d_in[6];
    const float* ow    = (const float*)d_in[7];
    const float* ob    = (const float*)d_in[8];

    float* out  = (float*)d_out;
    float* avgw = out + (long)T_DIM * B_DIM * E_DIM;

    uint32_t *Qp, *Kp, *Vp, *Cp;
    float *Pp;
    cudaGetSymbolAddress((void**)&Qp, g_Q);
    cudaGetSymbolAddress((void**)&Kp, g_K);
    cudaGetSymbolAddress((void**)&Vp, g_V);
    cudaGetSymbolAddress((void**)&Cp, g_Ctx);
    cudaGetSymbolAddress((void**)&Pp, g_P);

    cudaFuncSetAttribute(gemm_qkv,
        cudaFuncAttributeMaxDynamicSharedMemorySize, GEMM_SMEM_BYTES);
    cudaFuncSetAttribute(gemm_out,
        cudaFuncAttributeMaxDynamicSharedMemorySize, GEMM_SMEM_BYTES);
    cudaFuncSetAttribute(score_kernel,
        cudaFuncAttributeMaxDynamicSharedMemorySize, SCORE_SMEM_BYTES);
    cudaFuncSetAttribute(softmax_avg,
        cudaFuncAttributeMaxDynamicSharedMemorySize, SA_SMEM_BYTES);
    cudaFuncSetAttribute(pv_kernel,
        cudaFuncAttributeMaxDynamicSharedMemorySize, PV_SMEM_BYTES);

    gemm_qkv<<<dim3(24, 32), 256, GEMM_SMEM_BYTES>>>(
        query, key, value, ipw, ipb, Qp, Kp, Vp);

    score_kernel<<<dim3(8, 8, 64), 256, SCORE_SMEM_BYTES>>>(Qp, Kp, Pp);

    softmax_avg<<<B_DIM * T_DIM, 512, SA_SMEM_BYTES>>>(Pp, amask, pad, avgw);

    pv_kernel<<<dim3(8, 1, 64), 256, PV_SMEM_BYTES>>>(
        (const uint32_t*)Pp, Vp, Cp);

    gemm_out<<<dim3(8, 32), 256, GEMM_SMEM_BYTES>>>(Cp, ow, ob, out);
}